// round 1
// baseline (speedup 1.0000x reference)
#include <cuda_runtime.h>
#include <math.h>

#define RMIN 10
#define RMAX 50
#define GAP  40
#define RR   41
#define PP   128
#define NSTEP 32
#define BB   16384
#define MCN  10000
#define DT_F 0.03125f
#define PI_F 3.14159265358979323846f

// ---------------- device scratch (no allocations allowed) ----------------
__device__ float g_jm[RR * 80];      // normalized cumulative jump measure
__device__ float g_cr[RR];
__device__ float g_cfr[RR];
__device__ int   g_hist[RR * 80];    // MC histogram
__device__ float g_mcjump[RR * PP];  // mc_jump table
__device__ float g_upre[BB];         // u_pre after init NN

// ---------------- tables ----------------
__global__ void k_tables() {
    int r = threadIdx.x;
    if (r >= RR) return;
    float cum = 0.f, slam = 0.f, smu = 0.f;
    for (int k = 1; k <= GAP; k++) {
        float kk = (float)k;
        float lam = ((r + RMIN + k) <= RMAX) ? 1.0f / (kk * kk) : 0.0f;
        slam += lam;
        cum += lam;
        g_jm[r * 80 + (k - 1)] = cum;
    }
    for (int k = 1; k <= GAP; k++) {
        float kk = (float)k;
        float mu = ((r + RMIN - k) >= RMIN) ? 1.0f / (kk * kk) : 0.0f;
        smu += mu;
        cum += mu;
        g_jm[r * 80 + GAP + (k - 1)] = cum;
    }
    float cr = cum;
    g_cr[r] = cr;
    g_cfr[r] = slam + smu - cr;   // ~0 up to rounding, matches reference semantics
    for (int j = 0; j < 80; j++) g_jm[r * 80 + j] /= cr;
}

__global__ void k_zero_hist() {
    int i = blockIdx.x * blockDim.x + threadIdx.x;
    if (i < RR * 80) g_hist[i] = 0;
}

// MC sampling -> histogram of selected bins per radius
__global__ void k_mc_hist(const float* __restrict__ u_mc) {
    int i = blockIdx.x * blockDim.x + threadIdx.x;
    if (i >= MCN * RR) return;
    int r = i % RR;
    float u = u_mc[i];
    const float* row = &g_jm[r * 80];
    int cnt = 0;
#pragma unroll 8
    for (int j = 0; j < 80; j++) cnt += (u < row[j]) ? 1 : 0;
    int ind = 80 - cnt;            // 0..79
    atomicAdd(&g_hist[r * 80 + ind], 1);
}

// mc_jump[r,p] = (sum_b hist[r,b] * jump_l_flat[b,p]) / MC * cr[r]
__global__ void k_mc_combine(const float* __restrict__ jump_l) {
    int idx = blockIdx.x * blockDim.x + threadIdx.x;
    if (idx >= RR * PP) return;
    int r = idx / PP, p = idx % PP;
    float s = 0.f;
    for (int b = 0; b < 80; b++) {
        int c = g_hist[r * 80 + b];
        if (c) s += (float)c * jump_l[b * PP + p];  // flat (2,40,128) == b*128+p
    }
    g_mcjump[idx] = s * (1.0f / (float)MCN) * g_cr[r];
}

// ---------------- helpers ----------------
__device__ __forceinline__ void cp4(float* dst, const float* __restrict__ src,
                                    int nfl, int tid) {
    const float4* s = (const float4*)src;
    float4* d = (float4*)dst;
    int n4 = nfl >> 2;
    for (int i = tid; i < n4; i += 128) d[i] = s[i];
}

// FNN front: x(3) -> tanh(64) -> tanh(64).  Weight block layout (floats):
//   W1 @0 (3x64), b1 @192, W2 @256 (64x64), b2 @4352, W3 @4416 (64x128), b3 @12608
__device__ __forceinline__ void fnn_h2(const float* __restrict__ smw,
                                       float x0, float x1, float x2,
                                       float* h2) {
    const float* W1 = smw;
    const float* b1 = smw + 192;
    const float* W2 = smw + 256;
    const float* b2 = smw + 4352;
    float h1[64];
#pragma unroll
    for (int j = 0; j < 64; j += 4) {
        float4 wa = *(const float4*)(W1 + j);
        float4 wb = *(const float4*)(W1 + 64 + j);
        float4 wc = *(const float4*)(W1 + 128 + j);
        float4 bb = *(const float4*)(b1 + j);
        h1[j + 0] = tanhf(fmaf(x0, wa.x, fmaf(x1, wb.x, fmaf(x2, wc.x, bb.x))));
        h1[j + 1] = tanhf(fmaf(x0, wa.y, fmaf(x1, wb.y, fmaf(x2, wc.y, bb.y))));
        h1[j + 2] = tanhf(fmaf(x0, wa.z, fmaf(x1, wb.z, fmaf(x2, wc.z, bb.z))));
        h1[j + 3] = tanhf(fmaf(x0, wa.w, fmaf(x1, wb.w, fmaf(x2, wc.w, bb.w))));
    }
#pragma unroll
    for (int k = 0; k < 64; k += 4) {
        float4 a = *(const float4*)(b2 + k);
#pragma unroll
        for (int j = 0; j < 64; j++) {
            float4 w = *(const float4*)(W2 + j * 64 + k);
            a.x = fmaf(h1[j], w.x, a.x);
            a.y = fmaf(h1[j], w.y, a.y);
            a.z = fmaf(h1[j], w.z, a.z);
            a.w = fmaf(h1[j], w.w, a.w);
        }
        h2[k + 0] = tanhf(a.x);
        h2[k + 1] = tanhf(a.y);
        h2[k + 2] = tanhf(a.z);
        h2[k + 3] = tanhf(a.w);
    }
}

// ---------------- initial u_pre ----------------
// shared: weight block (12736 floats) + uE transposed [p][49] (6272 floats)
#define SMEM_INIT_FLOATS (12736 + 6272)
__global__ void __launch_bounds__(128, 1)
k_init_upre(const int* __restrict__ rt0, const float* __restrict__ xt0,
            const float* __restrict__ uW1, const float* __restrict__ ub1,
            const float* __restrict__ uW2, const float* __restrict__ ub2,
            const float* __restrict__ uW3, const float* __restrict__ ub3,
            const float* __restrict__ uE) {
    extern __shared__ float sm[];
    float* smw = sm;
    float* sE = sm + 12736;
    int tid = threadIdx.x;
    cp4(smw + 0, uW1, 192, tid);
    cp4(smw + 192, ub1, 64, tid);
    cp4(smw + 256, uW2, 4096, tid);
    cp4(smw + 4352, ub2, 64, tid);
    cp4(smw + 4416, uW3, 8192, tid);
    cp4(smw + 12608, ub3, 128, tid);
    for (int idx = tid; idx < RR * PP; idx += 128) {
        int r = idx / PP, p = idx % PP;
        sE[p * 49 + r] = uE[idx];   // uE (R,128,1)
    }
    __syncthreads();

    int i = blockIdx.x * 128 + tid;
    float x0 = xt0[i * 3 + 0], x1 = xt0[i * 3 + 1], x2 = xt0[i * 3 + 2];
    int ridx = rt0[i] - RMIN;
    float h2[64];
    fnn_h2(smw, x0, x1, x2, h2);
    const float* sW3 = smw + 4416;
    const float* sb3 = smw + 12608;
    float acc = 0.f;
#pragma unroll 1
    for (int p = 0; p < PP; p += 4) {
        float4 a = *(const float4*)(sb3 + p);
#pragma unroll
        for (int j = 0; j < 64; j++) {
            float4 w = *(const float4*)(sW3 + j * 128 + p);
            a.x = fmaf(h2[j], w.x, a.x);
            a.y = fmaf(h2[j], w.y, a.y);
            a.z = fmaf(h2[j], w.z, a.z);
            a.w = fmaf(h2[j], w.w, a.w);
        }
        const float* e = sE + p * 49 + ridx;
        acc = fmaf(a.x, e[0], acc);
        acc = fmaf(a.y, e[49], acc);
        acc = fmaf(a.z, e[98], acc);
        acc = fmaf(a.w, e[147], acc);
    }
    g_upre[i] = acc;
}

// ---------------- main time loop ----------------
// dynamic shared layout (floats):
//  0      : g-weights block (12736)
//  12736  : j-weights block (12736)
//  25472  : guE transposed  [(p*3+o)][49] -> 384*49 = 18816
//  44288  : jump_r  [p][49] -> 6272
//  50560  : mc_jump [p][49] -> 6272
//  56832  : cr (48)
//  56880  : cfr (48)
#define SMEM_MAIN_FLOATS 56928
__global__ void __launch_bounds__(128, 1)
k_main(const int* __restrict__ rt0, const float* __restrict__ xt0,
       const float* __restrict__ dBt, const float* __restrict__ u_jump,
       const float* __restrict__ u_size,
       const float* __restrict__ guW1, const float* __restrict__ gub1,
       const float* __restrict__ guW2, const float* __restrict__ gub2,
       const float* __restrict__ guW3, const float* __restrict__ gub3,
       const float* __restrict__ guE,
       const float* __restrict__ jxW1, const float* __restrict__ jxb1,
       const float* __restrict__ jxW2, const float* __restrict__ jxb2,
       const float* __restrict__ jxW3, const float* __restrict__ jxb3,
       const float* __restrict__ jump_r, const float* __restrict__ jump_l,
       float* __restrict__ out) {
    extern __shared__ float sm[];
    float* smG = sm;
    float* smJ = sm + 12736;
    float* sE  = sm + 25472;
    float* sJR = sm + 44288;
    float* sMC = sm + 50560;
    float* sCR = sm + 56832;
    float* sCF = sm + 56880;
    int tid = threadIdx.x;

    // persistent tables
    for (int idx = tid; idx < RR * PP; idx += 128) {
        int r = idx / PP, p = idx % PP;
        sJR[p * 49 + r] = jump_r[idx];
        sMC[p * 49 + r] = g_mcjump[idx];
    }
    for (int idx = tid; idx < RR; idx += 128) {
        sCR[idx] = g_cr[idx];
        sCF[idx] = g_cfr[idx];
    }

    int i = blockIdx.x * 128 + tid;
    int rt = rt0[i];
    float x0 = xt0[i * 3 + 0], x1 = xt0[i * 3 + 1], x2 = xt0[i * 3 + 2];
    float xi0 = x0, xi1 = x1, xi2 = x2;
    float g00 = 1.f, g01 = 0.f, g02 = 0.f;
    float g10 = 0.f, g11 = 1.f, g12 = 0.f;
    float g20 = 0.f, g21 = 0.f, g22 = 1.f;
    float upre = g_upre[i];
    float fun = 0.f;
    const float sqDT = 0.17677669529663688985f;  // sqrt(1/32)
    const float sq2D = 1.41421356237309504880f;  // sqrt(2)
    float h2[64];

#pragma unroll 1
    for (int t = 0; t < NSTEP; t++) {
        __syncthreads();
        // load per-step weights
        cp4(smG + 0,     guW1 + t * 192,  192,  tid);
        cp4(smG + 192,   gub1 + t * 64,   64,   tid);
        cp4(smG + 256,   guW2 + t * 4096, 4096, tid);
        cp4(smG + 4352,  gub2 + t * 64,   64,   tid);
        cp4(smG + 4416,  guW3 + t * 8192, 8192, tid);
        cp4(smG + 12608, gub3 + t * 128,  128,  tid);
        cp4(smJ + 0,     jxW1 + t * 192,  192,  tid);
        cp4(smJ + 192,   jxb1 + t * 64,   64,   tid);
        cp4(smJ + 256,   jxW2 + t * 4096, 4096, tid);
        cp4(smJ + 4352,  jxb2 + t * 64,   64,   tid);
        cp4(smJ + 4416,  jxW3 + t * 8192, 8192, tid);
        cp4(smJ + 12608, jxb3 + t * 128,  128,  tid);
        {
            const float* gEsrc = guE + (size_t)t * (RR * PP * 3);
            for (int idx = tid; idx < RR * PP * 3; idx += 128) {
                int r = idx / (PP * 3);
                int c = idx % (PP * 3);
                sE[c * 49 + r] = gEsrc[idx];
            }
        }
        __syncthreads();

        int ridx = rt - RMIN;
        float rtf = (float)rt;
        float uj = u_jump[t * BB + i];
        int drt = 0;
        if (uj < sCR[ridx] * DT_F) {
            float us = u_size[t * BB + i];
            const float* row = g_jm + ridx * 80;
            int cnt = 0;
#pragma unroll 8
            for (int j = 0; j < 80; j++) cnt += (us < row[j]) ? 1 : 0;
            int ind = 80 - cnt;
            drt = (ind < GAP) ? (ind + 1) : -(ind - GAP + 1);
        }

        // geometry
        float rn = sqrtf(x0 * x0 + x1 * x1 + x2 * x2);
        float cz = fminf(fmaxf(x2 / rn, -1.0f), 1.0f);
        float theta = acosf(cz) - 0.5f * PI_F;
        float phi = atan2f(x1, x0);
        float st, ct, sp, cpv;
        sincosf(theta, &st, &ct);
        sincosf(phi, &sp, &cpv);
        float T00 = cpv * ct, T01 = -sp,  T02 = cpv * st;
        float T10 = sp * ct,  T11 = cpv,  T12 = sp * st;
        float T20 = -st,      T21 = 0.f,  T22 = ct;

        // ---- gu = tnn(xt_in) with step weights ----
        fnn_h2(smG, xi0, xi1, xi2, h2);
        float gu0 = 0.f, gu1 = 0.f, gu2 = 0.f;
        {
            const float* sW3 = smG + 4416;
            const float* sb3 = smG + 12608;
#pragma unroll 1
            for (int p = 0; p < PP; p += 4) {
                float4 a = *(const float4*)(sb3 + p);
#pragma unroll
                for (int j = 0; j < 64; j++) {
                    float4 w = *(const float4*)(sW3 + j * 128 + p);
                    a.x = fmaf(h2[j], w.x, a.x);
                    a.y = fmaf(h2[j], w.y, a.y);
                    a.z = fmaf(h2[j], w.z, a.z);
                    a.w = fmaf(h2[j], w.w, a.w);
                }
                const float* e = sE + (p * 3) * 49 + ridx;
                gu0 = fmaf(a.x, e[0],   gu0);
                gu1 = fmaf(a.x, e[49],  gu1);
                gu2 = fmaf(a.x, e[98],  gu2);
                gu0 = fmaf(a.y, e[147], gu0);
                gu1 = fmaf(a.y, e[196], gu1);
                gu2 = fmaf(a.y, e[245], gu2);
                gu0 = fmaf(a.z, e[294], gu0);
                gu1 = fmaf(a.z, e[343], gu1);
                gu2 = fmaf(a.z, e[392], gu2);
                gu0 = fmaf(a.w, e[441], gu0);
                gu1 = fmaf(a.w, e[490], gu1);
                gu2 = fmaf(a.w, e[539], gu2);
            }
        }
        // v = gu . gt . Tinv
        float w0 = gu0 * g00 + gu1 * g10 + gu2 * g20;
        float w1 = gu0 * g01 + gu1 * g11 + gu2 * g21;
        float w2 = gu0 * g02 + gu1 * g12 + gu2 * g22;
        float v1 = w0 * T01 + w1 * T11 + w2 * T21;
        float v2 = w0 * T02 + w1 * T12 + w2 * T22;
        float ga = -v2, gb = v1;    // grad_u2

        // ---- jx fnn + jump term ----
        fnn_h2(smJ, xi0, xi1, xi2, h2);
        const float* jlrow = (const float*)0;
        if (drt > 0)      jlrow = jump_l + (drt - 1) * PP;
        else if (drt < 0) jlrow = jump_l + GAP * PP + (-drt - 1) * PP;
        float jmp = 0.f;
        {
            const float* sW3 = smJ + 4416;
            const float* sb3 = smJ + 12608;
#pragma unroll 1
            for (int p = 0; p < PP; p += 4) {
                float4 a = *(const float4*)(sb3 + p);
#pragma unroll
                for (int j = 0; j < 64; j++) {
                    float4 w = *(const float4*)(sW3 + j * 128 + p);
                    a.x = fmaf(h2[j], w.x, a.x);
                    a.y = fmaf(h2[j], w.y, a.y);
                    a.z = fmaf(h2[j], w.z, a.z);
                    a.w = fmaf(h2[j], w.w, a.w);
                }
                float jl0 = 0.f, jl1 = 0.f, jl2 = 0.f, jl3 = 0.f;
                if (jlrow) {
                    jl0 = jlrow[p];
                    jl1 = jlrow[p + 1];
                    jl2 = jlrow[p + 2];
                    jl3 = jlrow[p + 3];
                }
                const float* jr = sJR + p * 49 + ridx;
                const float* mc = sMC + p * 49 + ridx;
                jmp += (a.x * jr[0])   * (jl0 - mc[0]   * DT_F);
                jmp += (a.y * jr[49])  * (jl1 - mc[49]  * DT_F);
                jmp += (a.z * jr[98])  * (jl2 - mc[98]  * DT_F);
                jmp += (a.w * jr[147]) * (jl3 - mc[147] * DT_F);
            }
        }

        float2 dbv = ((const float2*)dBt)[t * BB + i];
        float dB0 = dbv.x * sqDT, dB1 = dbv.y * sqDT;
        float c1 = sq2D / rtf;
        float ef = expf(-fun);
        upre += ef * (c1 * (ga * dB0 + gb * dB1) + jmp);
        fun += sCF[ridx] * DT_F;

        float dX20 = c1 * dB0, dX21 = c1 * dB1;
        float th_d = dX20 + 0.5f * PI_F;
        float sth, cth, sph, cph;
        sincosf(th_d, &sth, &cth);
        sincosf(dX21, &sph, &cph);
        float d30 = sth * cph - 1.0f;
        float d31 = sth * sph;
        float d32 = cth;
        float dX0 = T00 * d30 + T01 * d31 + T02 * d32;
        float dX1 = T10 * d30 + T11 * d31 + T12 * d32;
        float dX2 = T20 * d30 + T21 * d31 + T22 * d32;
        x0 += dX0; x1 += dX1; x2 += dX2;
        xi0 += g00 * dX0 + g01 * dX1 + g02 * dX2;
        xi1 += g10 * dX0 + g11 * dX1 + g12 * dX2;
        xi2 += g20 * dX0 + g21 * dX1 + g22 * dX2;
        rt += drt;
        if (xi2 < 0.f) {
            xi2 = -xi2;
            g20 = -g20; g21 = -g21; g22 = -g22;
        }
    }

    float ef = expf(-fun);
    float ur = (xi0 * xi0 + xi1 * xi1 + xi2 * xi2) / (float)rt * ef;
    out[i] = upre;
    out[BB + i] = ur;
}

// ---------------- launcher ----------------
extern "C" void kernel_launch(void* const* d_in, const int* in_sizes, int n_in,
                              void* d_out, int out_size) {
    const int*   rt0    = (const int*)d_in[1];
    const float* xt0    = (const float*)d_in[2];
    const float* dBt    = (const float*)d_in[3];
    const float* u_jump = (const float*)d_in[4];
    const float* u_size = (const float*)d_in[5];
    const float* u_mc   = (const float*)d_in[6];
    const float* uW1 = (const float*)d_in[7];
    const float* ub1 = (const float*)d_in[8];
    const float* uW2 = (const float*)d_in[9];
    const float* ub2 = (const float*)d_in[10];
    const float* uW3 = (const float*)d_in[11];
    const float* ub3 = (const float*)d_in[12];
    const float* uE  = (const float*)d_in[13];
    const float* guW1 = (const float*)d_in[14];
    const float* gub1 = (const float*)d_in[15];
    const float* guW2 = (const float*)d_in[16];
    const float* gub2 = (const float*)d_in[17];
    const float* guW3 = (const float*)d_in[18];
    const float* gub3 = (const float*)d_in[19];
    const float* guE  = (const float*)d_in[20];
    const float* jxW1 = (const float*)d_in[21];
    const float* jxb1 = (const float*)d_in[22];
    const float* jxW2 = (const float*)d_in[23];
    const float* jxb2 = (const float*)d_in[24];
    const float* jxW3 = (const float*)d_in[25];
    const float* jxb3 = (const float*)d_in[26];
    const float* jump_r = (const float*)d_in[27];
    const float* jump_l = (const float*)d_in[28];
    float* out = (float*)d_out;

    cudaFuncSetAttribute(k_init_upre, cudaFuncAttributeMaxDynamicSharedMemorySize,
                         SMEM_INIT_FLOATS * 4);
    cudaFuncSetAttribute(k_main, cudaFuncAttributeMaxDynamicSharedMemorySize,
                         SMEM_MAIN_FLOATS * 4);

    k_tables<<<1, 64>>>();
    k_zero_hist<<<(RR * 80 + 255) / 256, 256>>>();
    k_mc_hist<<<(MCN * RR + 255) / 256, 256>>>(u_mc);
    k_mc_combine<<<(RR * PP + 127) / 128, 128>>>(jump_l);
    k_init_upre<<<BB / 128, 128, SMEM_INIT_FLOATS * 4>>>(rt0, xt0, uW1, ub1, uW2,
                                                         ub2, uW3, ub3, uE);
    k_main<<<BB / 128, 128, SMEM_MAIN_FLOATS * 4>>>(
        rt0, xt0, dBt, u_jump, u_size,
        guW1, gub1, guW2, gub2, guW3, gub3, guE,
        jxW1, jxb1, jxW2, jxb2, jxW3, jxb3,
        jump_r, jump_l, out);
    (void)in_sizes; (void)n_in; (void)out_size;
}

// round 3
// speedup vs baseline: 2.7403x; 2.7403x over previous
#include <cuda_runtime.h>
#include <math.h>

#define RMIN 10
#define GAP  40
#define RR   41
#define PP   128
#define NSTEP 32
#define BB   16384
#define MCN  10000
#define DT_F 0.03125f
#define PI_F 3.14159265358979323846f
#define NPAD 3328       // 41*81 = 3321 padded to 52*64
#define NBLK 52
#define CROW 68         // 64 coeffs + c0 + 3 pad (16B-aligned rows)

// ---------------- device scratch ----------------
__device__ float g_jm[RR * 80];
__device__ float g_cr[RR];
__device__ float g_cfr[RR];
__device__ int   g_hist[RR * 80];
__device__ float g_mcjump[RR * PP];
__device__ float g_W3Eu[RR * 64];
__device__ float g_b3Eu[RR];
__device__ float g_W3Eg[NSTEP * RR * 192];
__device__ float g_b3Eg[NSTEP * RR * 3];
__device__ float g_C[(size_t)NSTEP * NPAD * CROW];   // ~29 MB

// ---------------- tables (+ hist zero) ----------------
__global__ void k_tables() {
    int tid = threadIdx.x;
    for (int i = tid; i < RR * 80; i += 64) g_hist[i] = 0;
    int r = tid;
    if (r >= RR) return;
    float cum = 0.f, slam = 0.f, smu = 0.f;
    for (int k = 1; k <= GAP; k++) {
        float kk = (float)k;
        float lam = ((r + RMIN + k) <= RMIN + GAP) ? 1.0f / (kk * kk) : 0.0f;
        slam += lam; cum += lam;
        g_jm[r * 80 + (k - 1)] = cum;
    }
    for (int k = 1; k <= GAP; k++) {
        float kk = (float)k;
        float mu = ((r + RMIN - k) >= RMIN) ? 1.0f / (kk * kk) : 0.0f;
        smu += mu; cum += mu;
        g_jm[r * 80 + GAP + (k - 1)] = cum;
    }
    g_cr[r] = cum;
    g_cfr[r] = slam + smu - cum;
    for (int j = 0; j < 80; j++) g_jm[r * 80 + j] /= cum;
}

__global__ void k_mc_hist(const float* __restrict__ u_mc) {
    int i = blockIdx.x * blockDim.x + threadIdx.x;
    if (i >= MCN * RR) return;
    int r = i % RR;
    float u = u_mc[i];
    const float* row = &g_jm[r * 80];
    int cnt = 0;
#pragma unroll 8
    for (int j = 0; j < 80; j++) cnt += (u < row[j]) ? 1 : 0;
    atomicAdd(&g_hist[r * 80 + (80 - cnt)], 1);
}

__global__ void k_mc_combine(const float* __restrict__ jump_l) {
    int idx = blockIdx.x * blockDim.x + threadIdx.x;
    if (idx >= RR * PP) return;
    int r = idx / PP, p = idx % PP;
    float s = 0.f;
    for (int b = 0; b < 80; b++) {
        int c = g_hist[r * 80 + b];
        if (c) s += (float)c * jump_l[b * PP + p];
    }
    g_mcjump[idx] = s * (1.0f / (float)MCN) * g_cr[r];
}

// ---------------- W3E builds (g-NN per-step + u-NN) ----------------
__global__ void k_build_w3e(const float* __restrict__ guW3,
                            const float* __restrict__ gub3,
                            const float* __restrict__ guE,
                            const float* __restrict__ uW3,
                            const float* __restrict__ ub3,
                            const float* __restrict__ uE) {
    __shared__ float sE[384];
    int r = blockIdx.y, bx = blockIdx.x, tid = threadIdx.x;
    if (bx < NSTEP) {
        int t = bx;
        for (int idx = tid; idx < 384; idx += 192)
            sE[idx] = guE[((size_t)(t * RR + r)) * 384 + idx];
        __syncthreads();
        int j = tid / 3, o = tid - j * 3;
        const float* w = guW3 + (size_t)t * 8192 + j * 128;
        float acc = 0.f;
#pragma unroll 4
        for (int p = 0; p < 128; p++) acc = fmaf(w[p], sE[p * 3 + o], acc);
        g_W3Eg[((size_t)t * RR + r) * 192 + tid] = acc;
        if (tid < 3) {
            const float* b = gub3 + t * 128;
            float a = 0.f;
            for (int p = 0; p < 128; p++) a = fmaf(b[p], sE[p * 3 + tid], a);
            g_b3Eg[(t * RR + r) * 3 + tid] = a;
        }
    } else {
        for (int idx = tid; idx < 128; idx += 192) sE[idx] = uE[r * 128 + idx];
        __syncthreads();
        if (tid < 64) {
            const float* w = uW3 + tid * 128;
            float acc = 0.f;
#pragma unroll 4
            for (int p = 0; p < 128; p++) acc = fmaf(w[p], sE[p], acc);
            g_W3Eu[r * 64 + tid] = acc;
        }
        if (tid == 64) {
            float a = 0.f;
            for (int p = 0; p < 128; p++) a = fmaf(ub3[p], sE[p], a);
            g_b3Eu[r] = a;
        }
    }
}

// ---------------- C table build: C[t][n=r*81+d][j] + c0 ----------------
// C = jxW3[t] (64x128)  @  B[n] (128), B[n][p] = jr[r,p]*(jl'[d,p] - mc[r,p]*DT)
#define BPAD 133
#define SMEM_C_FLOATS (2 * 64 * BPAD)
__global__ void __launch_bounds__(256, 1)
k_build_C(const float* __restrict__ jxW3, const float* __restrict__ jxb3,
          const float* __restrict__ jump_r, const float* __restrict__ jump_l) {
    extern __shared__ float smc[];
    float* smA = smc;                // [64][133]
    float* smB = smc + 64 * BPAD;    // [64][133]
    int nblk = blockIdx.x, t = blockIdx.y, tid = threadIdx.x;

    for (int idx = tid; idx < 8192; idx += 256) {
        int j = idx >> 7, p = idx & 127;
        smA[j * BPAD + p] = jxW3[(size_t)t * 8192 + idx];
    }
    for (int idx = tid; idx < 8192; idx += 256) {
        int n = idx >> 7, p = idx & 127;
        int n_g = nblk * 64 + n;
        float b = 0.f;
        if (n_g < RR * 81) {
            int r = n_g / 81, d = n_g - r * 81;
            float jl = 0.f;
            if (d > 40)      jl = jump_l[(d - 41) * PP + p];
            else if (d < 40) jl = jump_l[(79 - d) * PP + p];
            b = jump_r[r * PP + p] * (jl - g_mcjump[r * PP + p] * DT_F);
        }
        smB[n * BPAD + p] = b;
    }
    __syncthreads();

    int tx = tid & 15, ty = tid >> 4;
    const float* Ab = smA + (ty * 4) * BPAD;
    const float* Bb = smB + (tx * 4) * BPAD;
    float acc[16];
#pragma unroll
    for (int q = 0; q < 16; q++) acc[q] = 0.f;
#pragma unroll 4
    for (int p = 0; p < 128; p++) {
        float a0 = Ab[p], a1 = Ab[BPAD + p], a2 = Ab[2 * BPAD + p], a3 = Ab[3 * BPAD + p];
        float b0 = Bb[p], b1 = Bb[BPAD + p], b2 = Bb[2 * BPAD + p], b3 = Bb[3 * BPAD + p];
        acc[0]  = fmaf(a0, b0, acc[0]);  acc[1]  = fmaf(a0, b1, acc[1]);
        acc[2]  = fmaf(a0, b2, acc[2]);  acc[3]  = fmaf(a0, b3, acc[3]);
        acc[4]  = fmaf(a1, b0, acc[4]);  acc[5]  = fmaf(a1, b1, acc[5]);
        acc[6]  = fmaf(a1, b2, acc[6]);  acc[7]  = fmaf(a1, b3, acc[7]);
        acc[8]  = fmaf(a2, b0, acc[8]);  acc[9]  = fmaf(a2, b1, acc[9]);
        acc[10] = fmaf(a2, b2, acc[10]); acc[11] = fmaf(a2, b3, acc[11]);
        acc[12] = fmaf(a3, b0, acc[12]); acc[13] = fmaf(a3, b1, acc[13]);
        acc[14] = fmaf(a3, b2, acc[14]); acc[15] = fmaf(a3, b3, acc[15]);
    }
#pragma unroll
    for (int ii = 0; ii < 4; ii++) {
        int j = ty * 4 + ii;
#pragma unroll
        for (int nn = 0; nn < 4; nn++) {
            int n_g = nblk * 64 + tx * 4 + nn;
            g_C[((size_t)t * NPAD + n_g) * CROW + j] = acc[ii * 4 + nn];
        }
    }
    if (tid < 64) {
        int n_g = nblk * 64 + tid;
        const float* Bn = smB + tid * BPAD;
        const float* b3 = jxb3 + t * 128;
        float c0 = 0.f;
#pragma unroll 4
        for (int p = 0; p < 128; p++) c0 = fmaf(b3[p], Bn[p], c0);
        size_t base = ((size_t)t * NPAD + n_g) * CROW;
        g_C[base + 64] = c0;
        g_C[base + 65] = 0.f; g_C[base + 66] = 0.f; g_C[base + 67] = 0.f;
    }
}

// ---------------- helpers ----------------
__device__ __forceinline__ void cp4(float* dst, const float* __restrict__ src,
                                    int nfl, int tid, int nthr) {
    const float4* s = (const float4*)src;
    float4* d = (float4*)dst;
    int n4 = nfl >> 2;
    for (int i = tid; i < n4; i += nthr) d[i] = s[i];
}

__device__ __forceinline__ float tanh_fast(float x) {
    float xc = fminf(fmaxf(x, -15.f), 15.f);
    float e = __expf(2.0f * xc);
    return __fdividef(e - 1.0f, e + 1.0f);
}

// front of FNN: x(3) -> tanh(64) -> tanh(64)
// block layout: W1 @0 (3x64), b1 @192, W2 @256 (64x64), b2 @4352  (4416 floats)
__device__ __forceinline__ void fnn_front(const float* __restrict__ smw,
                                          float x0, float x1, float x2,
                                          float* h2) {
    float h1[64];
    const float* W1 = smw;
    const float* b1 = smw + 192;
#pragma unroll
    for (int j = 0; j < 64; j += 4) {
        float4 wa = *(const float4*)(W1 + j);
        float4 wb = *(const float4*)(W1 + 64 + j);
        float4 wc = *(const float4*)(W1 + 128 + j);
        float4 bb = *(const float4*)(b1 + j);
        h1[j + 0] = tanh_fast(fmaf(x0, wa.x, fmaf(x1, wb.x, fmaf(x2, wc.x, bb.x))));
        h1[j + 1] = tanh_fast(fmaf(x0, wa.y, fmaf(x1, wb.y, fmaf(x2, wc.y, bb.y))));
        h1[j + 2] = tanh_fast(fmaf(x0, wa.z, fmaf(x1, wb.z, fmaf(x2, wc.z, bb.z))));
        h1[j + 3] = tanh_fast(fmaf(x0, wa.w, fmaf(x1, wb.w, fmaf(x2, wc.w, bb.w))));
    }
    const float* W2 = smw + 256;
    const float* b2 = smw + 4352;
#pragma unroll 1
    for (int k = 0; k < 64; k += 16) {
        float acc[16];
#pragma unroll
        for (int q = 0; q < 16; q += 4) {
            float4 bb = *(const float4*)(b2 + k + q);
            acc[q] = bb.x; acc[q + 1] = bb.y; acc[q + 2] = bb.z; acc[q + 3] = bb.w;
        }
#pragma unroll
        for (int j = 0; j < 64; j++) {
            float hj = h1[j];
#pragma unroll
            for (int q = 0; q < 16; q += 4) {
                float4 w = *(const float4*)(W2 + j * 64 + k + q);
                acc[q]     = fmaf(hj, w.x, acc[q]);
                acc[q + 1] = fmaf(hj, w.y, acc[q + 1]);
                acc[q + 2] = fmaf(hj, w.z, acc[q + 2]);
                acc[q + 3] = fmaf(hj, w.w, acc[q + 3]);
            }
        }
#pragma unroll
        for (int q = 0; q < 16; q++) h2[k + q] = tanh_fast(acc[q]);
    }
}

// ---------------- main kernel ----------------
// dynamic smem layout (floats):
#define SM_GW   0          // 4416
#define SM_JW   4416       // 4416
#define SM_E    8832       // [192][41] = 7872  (pre-loop: W3Eu [64][41])
#define SM_B3E  16704      // [3][41] -> 128 slot
#define SM_JM   16832      // 41*80 = 13120
#define SM_CR   29952      // 44
#define SM_CF   29996      // 44
#define SM_XI0  30040
#define SM_XI1  30168
#define SM_XI2  30296
#define SM_JMP  30424
#define SM_RIDX 30552      // int
#define SM_D    30680      // int
#define SM_TOT  30808

__global__ void __launch_bounds__(256, 1)
k_main(const int* __restrict__ rt0, const float* __restrict__ xt0,
       const float* __restrict__ dBt, const float* __restrict__ u_jump,
       const float* __restrict__ u_size,
       const float* __restrict__ uW1, const float* __restrict__ ub1,
       const float* __restrict__ uW2, const float* __restrict__ ub2,
       const float* __restrict__ guW1, const float* __restrict__ gub1,
       const float* __restrict__ guW2, const float* __restrict__ gub2,
       const float* __restrict__ jxW1, const float* __restrict__ jxb1,
       const float* __restrict__ jxW2, const float* __restrict__ jxb2,
       float* __restrict__ out) {
    extern __shared__ float sm[];
    int* smi = (int*)sm;
    int tid = threadIdx.x;
    bool isg = tid < 128;
    int s = tid & 127;
    int i = blockIdx.x * 128 + s;

    // persistent tables
    for (int idx = tid; idx < RR * 80; idx += 256) sm[SM_JM + idx] = g_jm[idx];
    for (int idx = tid; idx < RR; idx += 256) {
        sm[SM_CR + idx] = g_cr[idx];
        sm[SM_CF + idx] = g_cfr[idx];
    }
    // u-NN front weights + W3Eu (transposed [j][41])
    cp4(sm + SM_GW, uW1, 192, tid, 256);
    cp4(sm + SM_GW + 192, ub1, 64, tid, 256);
    cp4(sm + SM_GW + 256, uW2, 4096, tid, 256);
    cp4(sm + SM_GW + 4352, ub2, 64, tid, 256);
    for (int idx = tid; idx < RR * 64; idx += 256) {
        int r = idx >> 6, j = idx & 63;
        sm[SM_E + j * 41 + r] = g_W3Eu[idx];
    }
    for (int idx = tid; idx < RR; idx += 256) sm[SM_B3E + idx] = g_b3Eu[idx];

    int rt = 0, drt = 0;
    float x0 = 0.f, x1 = 0.f, x2 = 0.f, xi0 = 0.f, xi1 = 0.f, xi2 = 0.f;
    float sgn = 1.f, upre = 0.f, fun = 0.f;
    const float sqDT = 0.17677669529663688985f;   // sqrt(1/32)
    const float sq2D = 1.41421356237309504880f;   // sqrt(2)
    float h2[64];

    if (isg) {
        rt = rt0[i];
        x0 = xt0[i * 3 + 0]; x1 = xt0[i * 3 + 1]; x2 = xt0[i * 3 + 2];
        xi0 = x0; xi1 = x1; xi2 = x2;
    }
    __syncthreads();

    // initial u_pre (g-threads) using u-NN weights currently in SM_GW/SM_E
    if (isg) {
        int r0 = rt - RMIN;
        fnn_front(sm + SM_GW, xi0, xi1, xi2, h2);
        upre = sm[SM_B3E + r0];
#pragma unroll
        for (int j = 0; j < 64; j++) upre = fmaf(h2[j], sm[SM_E + j * 41 + r0], upre);
    }

#pragma unroll 1
    for (int t = 0; t < NSTEP; t++) {
        // A: g computes drt + publishes xi/ridx/d
        if (isg) {
            int ridx = rt - RMIN;
            float uj = u_jump[t * BB + i];
            drt = 0;
            if (uj < sm[SM_CR + ridx] * DT_F) {
                float us = u_size[t * BB + i];
                const float* row = sm + SM_JM + ridx * 80;
                int cnt = 0;
#pragma unroll 8
                for (int j = 0; j < 80; j++) cnt += (us < row[j]) ? 1 : 0;
                int ind = 80 - cnt;
                drt = (ind < GAP) ? (ind + 1) : -(ind - GAP + 1);
            }
            sm[SM_XI0 + s] = xi0; sm[SM_XI1 + s] = xi1; sm[SM_XI2 + s] = xi2;
            smi[SM_RIDX + s] = ridx;
            smi[SM_D + s] = drt + 40;
        }
        __syncthreads();   // sync1: prev-step weight readers done; xchg published

        // B: load per-step weights + W3Eg tables
        cp4(sm + SM_GW,        guW1 + t * 192,  192,  tid, 256);
        cp4(sm + SM_GW + 192,  gub1 + t * 64,   64,   tid, 256);
        cp4(sm + SM_GW + 256,  guW2 + t * 4096, 4096, tid, 256);
        cp4(sm + SM_GW + 4352, gub2 + t * 64,   64,   tid, 256);
        cp4(sm + SM_JW,        jxW1 + t * 192,  192,  tid, 256);
        cp4(sm + SM_JW + 192,  jxb1 + t * 64,   64,   tid, 256);
        cp4(sm + SM_JW + 256,  jxW2 + t * 4096, 4096, tid, 256);
        cp4(sm + SM_JW + 4352, jxb2 + t * 64,   64,   tid, 256);
        {
            const float* wsrc = g_W3Eg + (size_t)t * RR * 192;
            for (int idx = tid; idx < RR * 192; idx += 256) {
                int r = idx / 192, c = idx - r * 192;
                sm[SM_E + c * 41 + r] = wsrc[idx];
            }
            const float* bsrc = g_b3Eg + t * RR * 3;
            for (int idx = tid; idx < RR * 3; idx += 256) {
                int r = idx / 3, o = idx - r * 3;
                sm[SM_B3E + o * 41 + r] = bsrc[idx];
            }
        }
        __syncthreads();   // sync2: weights ready

        float X0 = sm[SM_XI0 + s], X1 = sm[SM_XI1 + s], X2 = sm[SM_XI2 + s];
        int ridx = smi[SM_RIDX + s];
        fnn_front(isg ? sm + SM_GW : sm + SM_JW, X0, X1, X2, h2);

        float T00 = 0, T01 = 0, T02 = 0, T10 = 0, T11 = 0, T12 = 0, T20 = 0, T22 = 0;
        float ga = 0.f, gb = 0.f;
        if (isg) {
            // geometry from xt
            float rn = sqrtf(x0 * x0 + x1 * x1 + x2 * x2);
            float cz = fminf(fmaxf(x2 / rn, -1.0f), 1.0f);
            float theta = acosf(cz) - 0.5f * PI_F;
            float phi = atan2f(x1, x0);
            float st, ct, sp, cpv;
            sincosf(theta, &st, &ct);
            sincosf(phi, &sp, &cpv);
            T00 = cpv * ct; T01 = -sp;  T02 = cpv * st;
            T10 = sp * ct;  T11 = cpv;  T12 = sp * st;
            T20 = -st;      T22 = ct;
            // gu = h2 @ W3E[ridx] + b3E[ridx]
            float gu0 = sm[SM_B3E + ridx];
            float gu1 = sm[SM_B3E + 41 + ridx];
            float gu2 = sm[SM_B3E + 82 + ridx];
#pragma unroll
            for (int j = 0; j < 64; j++) {
                const float* e = sm + SM_E + (j * 3) * 41 + ridx;
                gu0 = fmaf(h2[j], e[0], gu0);
                gu1 = fmaf(h2[j], e[41], gu1);
                gu2 = fmaf(h2[j], e[82], gu2);
            }
            // v = (gu0, gu1, sgn*gu2) @ Tinv   (gt = diag(1,1,sgn))
            float w2s = sgn * gu2;
            float v1 = gu0 * T01 + gu1 * T11;             // T21 = 0
            float v2 = gu0 * T02 + gu1 * T12 + w2s * T22;
            ga = -v2; gb = v1;
        } else {
            int d = smi[SM_D + s];
            const float4* crow =
                (const float4*)(g_C + ((size_t)t * NPAD + ridx * 81 + d) * CROW);
            float jmp = crow[16].x;   // c0
#pragma unroll
            for (int q = 0; q < 16; q++) {
                float4 cv = crow[q];
                jmp = fmaf(h2[4 * q + 0], cv.x, jmp);
                jmp = fmaf(h2[4 * q + 1], cv.y, jmp);
                jmp = fmaf(h2[4 * q + 2], cv.z, jmp);
                jmp = fmaf(h2[4 * q + 3], cv.w, jmp);
            }
            sm[SM_JMP + s] = jmp;
        }
        __syncthreads();   // sync3: jmp ready

        if (isg) {
            float jmp = sm[SM_JMP + s];
            float2 db = ((const float2*)dBt)[t * BB + i];
            float dB0 = db.x * sqDT, dB1 = db.y * sqDT;
            float rtf = (float)rt;
            float c1 = sq2D / rtf;
            float ef = expf(-fun);
            upre = fmaf(ef, fmaf(c1, ga * dB0 + gb * dB1, jmp), upre);
            fun += sm[SM_CF + ridx] * DT_F;

            float dX20 = c1 * dB0, dX21 = c1 * dB1;
            float th_d = dX20 + 0.5f * PI_F;
            float sth, cth, sph, cph;
            sincosf(th_d, &sth, &cth);
            sincosf(dX21, &sph, &cph);
            float d30 = sth * cph - 1.0f;
            float d31 = sth * sph;
            float d32 = cth;
            float dX0 = T00 * d30 + T01 * d31 + T02 * d32;
            float dX1 = T10 * d30 + T11 * d31 + T12 * d32;
            float dX2 = T20 * d30 + T22 * d32;   // T21 = 0
            x0 += dX0; x1 += dX1; x2 += dX2;
            xi0 += dX0; xi1 += dX1; xi2 += sgn * dX2;
            rt += drt;
            if (xi2 < 0.f) { xi2 = -xi2; sgn = -sgn; }
        }
    }

    if (isg) {
        float ef = expf(-fun);
        float ur = (xi0 * xi0 + xi1 * xi1 + xi2 * xi2) / (float)rt * ef;
        out[i] = upre;
        out[BB + i] = ur;
    }
}

// ---------------- launcher ----------------
extern "C" void kernel_launch(void* const* d_in, const int* in_sizes, int n_in,
                              void* d_out, int out_size) {
    const int*   rt0    = (const int*)d_in[1];
    const float* xt0    = (const float*)d_in[2];
    const float* dBt    = (const float*)d_in[3];
    const float* u_jump = (const float*)d_in[4];
    const float* u_size = (const float*)d_in[5];
    const float* u_mc   = (const float*)d_in[6];
    const float* uW1 = (const float*)d_in[7];
    const float* ub1 = (const float*)d_in[8];
    const float* uW2 = (const float*)d_in[9];
    const float* ub2 = (const float*)d_in[10];
    const float* uW3 = (const float*)d_in[11];
    const float* ub3 = (const float*)d_in[12];
    const float* uE  = (const float*)d_in[13];
    const float* guW1 = (const float*)d_in[14];
    const float* gub1 = (const float*)d_in[15];
    const float* guW2 = (const float*)d_in[16];
    const float* gub2 = (const float*)d_in[17];
    const float* guW3 = (const float*)d_in[18];
    const float* gub3 = (const float*)d_in[19];
    const float* guE  = (const float*)d_in[20];
    const float* jxW1 = (const float*)d_in[21];
    const float* jxb1 = (const float*)d_in[22];
    const float* jxW2 = (const float*)d_in[23];
    const float* jxb2 = (const float*)d_in[24];
    const float* jxW3 = (const float*)d_in[25];
    const float* jxb3 = (const float*)d_in[26];
    const float* jump_r = (const float*)d_in[27];
    const float* jump_l = (const float*)d_in[28];
    float* out = (float*)d_out;

    cudaFuncSetAttribute(k_build_C, cudaFuncAttributeMaxDynamicSharedMemorySize,
                         SMEM_C_FLOATS * 4);
    cudaFuncSetAttribute(k_main, cudaFuncAttributeMaxDynamicSharedMemorySize,
                         SM_TOT * 4);

    k_tables<<<1, 64>>>();
    k_mc_hist<<<(MCN * RR + 255) / 256, 256>>>(u_mc);
    k_mc_combine<<<(RR * PP + 127) / 128, 128>>>(jump_l);
    k_build_w3e<<<dim3(NSTEP + 1, RR), 192>>>(guW3, gub3, guE, uW3, ub3, uE);
    k_build_C<<<dim3(NBLK, NSTEP), 256, SMEM_C_FLOATS * 4>>>(jxW3, jxb3, jump_r, jump_l);
    k_main<<<BB / 128, 256, SM_TOT * 4>>>(
        rt0, xt0, dBt, u_jump, u_size,
        uW1, ub1, uW2, ub2,
        guW1, gub1, guW2, gub2,
        jxW1, jxb1, jxW2, jxb2, out);
    (void)in_sizes; (void)n_in; (void)out_size;
}

// round 4
// speedup vs baseline: 3.1022x; 1.1321x over previous
#include <cuda_runtime.h>
#include <math.h>

#define RMIN 10
#define GAP  40
#define RR   41
#define PP   128
#define NSTEP 32
#define BB   16384
#define MCN  10000
#define DT_F 0.03125f
#define PI_F 3.14159265358979323846f
#define NPAD 3328       // 41*81 = 3321 padded
#define NBLK 52
#define CROW 68         // 64 coeffs + c0 + 3 pad

// ---------------- device scratch ----------------
__device__ float g_jm[RR * 80];
__device__ float g_cr[RR];
__device__ float g_cfr[RR];
__device__ int   g_hist[RR * 80];
__device__ float g_mcjump[RR * PP];
__device__ float g_W3Eu[RR * 64];
__device__ float g_b3Eu[RR];
__device__ float g_W3Eg[NSTEP * RR * 192];
__device__ float g_b3Eg[NSTEP * RR * 3];
__device__ float g_C[(size_t)NSTEP * NPAD * CROW];   // ~29 MB
__device__ float4 g_A[NSTEP * BB];                   // xi0,xi1,xi2, ef
__device__ float4 g_M[NSTEP * BB];                   // m0,m1,m2, bits(ridx|d<<8)
__device__ float  g_part[(NSTEP + 1) * BB];

// ---------------- tables (+ hist zero) ----------------
__global__ void k_tables() {
    int tid = threadIdx.x;
    for (int i = tid; i < RR * 80; i += 64) g_hist[i] = 0;
    int r = tid;
    if (r >= RR) return;
    float cum = 0.f, slam = 0.f, smu = 0.f;
    for (int k = 1; k <= GAP; k++) {
        float kk = (float)k;
        float lam = ((r + RMIN + k) <= RMIN + GAP) ? 1.0f / (kk * kk) : 0.0f;
        slam += lam; cum += lam;
        g_jm[r * 80 + (k - 1)] = cum;
    }
    for (int k = 1; k <= GAP; k++) {
        float kk = (float)k;
        float mu = ((r + RMIN - k) >= RMIN) ? 1.0f / (kk * kk) : 0.0f;
        smu += mu; cum += mu;
        g_jm[r * 80 + GAP + (k - 1)] = cum;
    }
    g_cr[r] = cum;
    g_cfr[r] = slam + smu - cum;
    for (int j = 0; j < 80; j++) g_jm[r * 80 + j] /= cum;
}

__global__ void k_mc_hist(const float* __restrict__ u_mc) {
    int i = blockIdx.x * blockDim.x + threadIdx.x;
    if (i >= MCN * RR) return;
    int r = i % RR;
    float u = u_mc[i];
    const float* row = &g_jm[r * 80];
    int cnt = 0;
#pragma unroll 8
    for (int j = 0; j < 80; j++) cnt += (u < row[j]) ? 1 : 0;
    atomicAdd(&g_hist[r * 80 + (80 - cnt)], 1);
}

__global__ void k_mc_combine(const float* __restrict__ jump_l) {
    int idx = blockIdx.x * blockDim.x + threadIdx.x;
    if (idx >= RR * PP) return;
    int r = idx / PP, p = idx % PP;
    float s = 0.f;
    for (int b = 0; b < 80; b++) {
        int c = g_hist[r * 80 + b];
        if (c) s += (float)c * jump_l[b * PP + p];
    }
    g_mcjump[idx] = s * (1.0f / (float)MCN) * g_cr[r];
}

// ---------------- W3E builds: one CTA per t (t=32 -> u-slice) ----------------
// smem: sW [64][129] (8256) + sE (15744 for t<32, 5248 for u)  -> 24000 floats
#define SMEM_W3E_FLOATS 24000
__global__ void __launch_bounds__(256, 1)
k_build_w3e(const float* __restrict__ guW3, const float* __restrict__ gub3,
            const float* __restrict__ guE,
            const float* __restrict__ uW3, const float* __restrict__ ub3,
            const float* __restrict__ uE) {
    extern __shared__ float smw[];
    float* sW = smw;             // [64][129]
    float* sE = smw + 8256;
    int t = blockIdx.x, tid = threadIdx.x;
    if (t < NSTEP) {
        for (int idx = tid; idx < 8192; idx += 256) {
            int j = idx >> 7, p = idx & 127;
            sW[j * 129 + p] = guW3[(size_t)t * 8192 + idx];
        }
        for (int idx = tid; idx < RR * 384; idx += 256)
            sE[idx] = guE[(size_t)t * RR * 384 + idx];
        __syncthreads();
        for (int idx = tid; idx < RR * 192; idx += 256) {
            int r = idx / 192, c = idx - r * 192;
            int j = c / 3, o = c - j * 3;
            const float* w = sW + j * 129;
            const float* e = sE + r * 384 + o;
            float acc = 0.f;
#pragma unroll 8
            for (int p = 0; p < 128; p++) acc = fmaf(w[p], e[p * 3], acc);
            g_W3Eg[((size_t)t * RR + r) * 192 + c] = acc;
        }
        if (tid < RR * 3) {
            int r = tid / 3, o = tid - r * 3;
            const float* b = gub3 + t * 128;
            const float* e = sE + r * 384 + o;
            float acc = 0.f;
            for (int p = 0; p < 128; p++) acc = fmaf(b[p], e[p * 3], acc);
            g_b3Eg[(t * RR + r) * 3 + o] = acc;
        }
    } else {
        for (int idx = tid; idx < 8192; idx += 256) {
            int j = idx >> 7, p = idx & 127;
            sW[j * 129 + p] = uW3[idx];
        }
        for (int idx = tid; idx < RR * 128; idx += 256) sE[idx] = uE[idx];
        __syncthreads();
        for (int idx = tid; idx < RR * 64; idx += 256) {
            int r = idx >> 6, j = idx & 63;
            const float* w = sW + j * 129;
            const float* e = sE + r * 128;
            float acc = 0.f;
#pragma unroll 8
            for (int p = 0; p < 128; p++) acc = fmaf(w[p], e[p], acc);
            g_W3Eu[r * 64 + j] = acc;
        }
        if (tid < RR) {
            const float* e = sE + tid * 128;
            float acc = 0.f;
            for (int p = 0; p < 128; p++) acc = fmaf(ub3[p], e[p], acc);
            g_b3Eu[tid] = acc;
        }
    }
}

// ---------------- C table build (transposed [p][.] staging) ----------------
#define CPAD 68
#define SMEM_C_FLOATS (2 * 128 * CPAD)
__global__ void __launch_bounds__(256, 1)
k_build_C(const float* __restrict__ jxW3, const float* __restrict__ jxb3,
          const float* __restrict__ jump_r, const float* __restrict__ jump_l) {
    extern __shared__ float smc[];
    float* smA = smc;                 // [128][68]: smA[p][j]
    float* smB = smc + 128 * CPAD;    // [128][68]: smB[p][n]
    int nblk = blockIdx.x, t = blockIdx.y, tid = threadIdx.x;

    for (int idx = tid; idx < 8192; idx += 256) {
        int j = idx >> 7, p = idx & 127;
        smA[p * CPAD + j] = jxW3[(size_t)t * 8192 + idx];
    }
    for (int idx = tid; idx < 8192; idx += 256) {
        int n = idx >> 7, p = idx & 127;
        int n_g = nblk * 64 + n;
        float b = 0.f;
        if (n_g < RR * 81) {
            int r = n_g / 81, d = n_g - r * 81;
            float jl = 0.f;
            if (d > 40)      jl = jump_l[(d - 41) * PP + p];
            else if (d < 40) jl = jump_l[(79 - d) * PP + p];
            b = jump_r[r * PP + p] * (jl - g_mcjump[r * PP + p] * DT_F);
        }
        smB[p * CPAD + n] = b;
    }
    __syncthreads();

    int tx = tid & 15, ty = tid >> 4;
    float acc[16];
#pragma unroll
    for (int q = 0; q < 16; q++) acc[q] = 0.f;
#pragma unroll 4
    for (int p = 0; p < 128; p++) {
        float4 av = *(const float4*)(smA + p * CPAD + ty * 4);
        float4 bv = *(const float4*)(smB + p * CPAD + tx * 4);
        acc[0]  = fmaf(av.x, bv.x, acc[0]);  acc[1]  = fmaf(av.x, bv.y, acc[1]);
        acc[2]  = fmaf(av.x, bv.z, acc[2]);  acc[3]  = fmaf(av.x, bv.w, acc[3]);
        acc[4]  = fmaf(av.y, bv.x, acc[4]);  acc[5]  = fmaf(av.y, bv.y, acc[5]);
        acc[6]  = fmaf(av.y, bv.z, acc[6]);  acc[7]  = fmaf(av.y, bv.w, acc[7]);
        acc[8]  = fmaf(av.z, bv.x, acc[8]);  acc[9]  = fmaf(av.z, bv.y, acc[9]);
        acc[10] = fmaf(av.z, bv.z, acc[10]); acc[11] = fmaf(av.z, bv.w, acc[11]);
        acc[12] = fmaf(av.w, bv.x, acc[12]); acc[13] = fmaf(av.w, bv.y, acc[13]);
        acc[14] = fmaf(av.w, bv.z, acc[14]); acc[15] = fmaf(av.w, bv.w, acc[15]);
    }
#pragma unroll
    for (int ii = 0; ii < 4; ii++) {
        int j = ty * 4 + ii;
#pragma unroll
        for (int nn = 0; nn < 4; nn++) {
            int n_g = nblk * 64 + tx * 4 + nn;
            g_C[((size_t)t * NPAD + n_g) * CROW + j] = acc[ii * 4 + nn];
        }
    }
    if (tid < 64) {
        int n_g = nblk * 64 + tid;
        const float* b3 = jxb3 + t * 128;
        float c0 = 0.f;
#pragma unroll 4
        for (int p = 0; p < 128; p++) c0 = fmaf(b3[p], smB[p * CPAD + tid], c0);
        size_t base = ((size_t)t * NPAD + n_g) * CROW;
        g_C[base + 64] = c0;
        g_C[base + 65] = 0.f; g_C[base + 66] = 0.f; g_C[base + 67] = 0.f;
    }
}

// ---------------- geometry pass: trajectory only, NN-free ----------------
__global__ void __launch_bounds__(256)
k_geom(const int* __restrict__ rt0, const float* __restrict__ xt0,
       const float* __restrict__ dBt, const float* __restrict__ u_jump,
       const float* __restrict__ u_size, float* __restrict__ out) {
    int i = blockIdx.x * 256 + threadIdx.x;
    const float sqDT = 0.17677669529663688985f;   // sqrt(1/32)
    const float sq2D = 1.41421356237309504880f;   // sqrt(2)
    int rt = rt0[i];
    float x0 = xt0[i * 3 + 0], x1 = xt0[i * 3 + 1], x2 = xt0[i * 3 + 2];
    float xi0 = x0, xi1 = x1, xi2 = x2;
    float sgn = 1.f, fun = 0.f;

#pragma unroll 1
    for (int t = 0; t < NSTEP; t++) {
        int ridx = rt - RMIN;
        float uj = u_jump[t * BB + i];
        int drt = 0;
        if (uj < g_cr[ridx] * DT_F) {
            float us = u_size[t * BB + i];
            const float* row = g_jm + ridx * 80;
            int cnt = 0;
#pragma unroll 8
            for (int j = 0; j < 80; j++) cnt += (us < row[j]) ? 1 : 0;
            int ind = 80 - cnt;
            drt = (ind < GAP) ? (ind + 1) : -(ind - GAP + 1);
        }

        float rn = sqrtf(x0 * x0 + x1 * x1 + x2 * x2);
        float cz = fminf(fmaxf(x2 / rn, -1.0f), 1.0f);
        float theta = acosf(cz) - 0.5f * PI_F;
        float phi = atan2f(x1, x0);
        float st, ct, sp, cpv;
        sincosf(theta, &st, &ct);
        sincosf(phi, &sp, &cpv);
        float T00 = cpv * ct, T01 = -sp,  T02 = cpv * st;
        float T10 = sp * ct,  T11 = cpv,  T12 = sp * st;
        float T20 = -st,      T22 = ct;

        float2 db = ((const float2*)dBt)[t * BB + i];
        float dB0 = db.x * sqDT, dB1 = db.y * sqDT;
        float rtf = (float)rt;
        float c1 = sq2D / rtf;
        float ef = expf(-fun);

        float m0 = ef * c1 * (T01 * dB1 - T02 * dB0);
        float m1 = ef * c1 * (T11 * dB1 - T12 * dB0);
        float m2 = -ef * c1 * sgn * T22 * dB0;
        float4 av; av.x = xi0; av.y = xi1; av.z = xi2; av.w = ef;
        g_A[t * BB + i] = av;
        float4 mv; mv.x = m0; mv.y = m1; mv.z = m2;
        mv.w = __int_as_float(ridx | ((drt + 40) << 8));
        g_M[t * BB + i] = mv;

        fun += g_cfr[ridx] * DT_F;

        float dX20 = c1 * dB0, dX21 = c1 * dB1;
        float th_d = dX20 + 0.5f * PI_F;
        float sth, cth, sph, cph;
        sincosf(th_d, &sth, &cth);
        sincosf(dX21, &sph, &cph);
        float d30 = sth * cph - 1.0f;
        float d31 = sth * sph;
        float d32 = cth;
        float dX0 = T00 * d30 + T01 * d31 + T02 * d32;
        float dX1 = T10 * d30 + T11 * d31 + T12 * d32;
        float dX2 = T20 * d30 + T22 * d32;     // T21 = 0
        x0 += dX0; x1 += dX1; x2 += dX2;
        xi0 += dX0; xi1 += dX1; xi2 += sgn * dX2;
        rt += drt;
        if (xi2 < 0.f) { xi2 = -xi2; sgn = -sgn; }
    }

    float ef = expf(-fun);
    out[BB + i] = (xi0 * xi0 + xi1 * xi1 + xi2 * xi2) / (float)rt * ef;
}

// ---------------- helpers ----------------
__device__ __forceinline__ void cp4s(float* dst, const float* __restrict__ src,
                                     int nfl, int tid) {
    const float4* s = (const float4*)src;
    float4* d = (float4*)dst;
    int n4 = nfl >> 2;
    for (int i = tid; i < n4; i += 256) d[i] = s[i];
}

__device__ __forceinline__ float tanh_fast(float x) {
    float xc = fminf(fmaxf(x, -15.f), 15.f);
    float e = __expf(2.0f * xc);
    return __fdividef(e - 1.0f, e + 1.0f);
}

// layer1: x(3) -> tanh(64); weights W1 @0 [3][64], b1 @192
__device__ __forceinline__ void layer1(const float* __restrict__ W,
                                       float x0, float x1, float x2, float* h1) {
#pragma unroll
    for (int j = 0; j < 64; j += 4) {
        float4 wa = *(const float4*)(W + j);
        float4 wb = *(const float4*)(W + 64 + j);
        float4 wc = *(const float4*)(W + 128 + j);
        float4 bb = *(const float4*)(W + 192 + j);
        h1[j + 0] = tanh_fast(fmaf(x0, wa.x, fmaf(x1, wb.x, fmaf(x2, wc.x, bb.x))));
        h1[j + 1] = tanh_fast(fmaf(x0, wa.y, fmaf(x1, wb.y, fmaf(x2, wc.y, bb.y))));
        h1[j + 2] = tanh_fast(fmaf(x0, wa.z, fmaf(x1, wb.z, fmaf(x2, wc.z, bb.z))));
        h1[j + 3] = tanh_fast(fmaf(x0, wa.w, fmaf(x1, wb.w, fmaf(x2, wc.w, bb.w))));
    }
}

// ---------------- NN kernel: grid (chunks, t) ----------------
// smem: gW 4416 | jW 4416 | E 7872 | B3E 128  = 16832 floats
#define SN_GW   0
#define SN_JW   4416
#define SN_E    8832
#define SN_B3E  16704
#define SN_TOT  16832
__global__ void __launch_bounds__(256, 2)
k_nn(const float* __restrict__ xt0, const int* __restrict__ rt0,
     const float* __restrict__ uW1, const float* __restrict__ ub1,
     const float* __restrict__ uW2, const float* __restrict__ ub2,
     const float* __restrict__ guW1, const float* __restrict__ gub1,
     const float* __restrict__ guW2, const float* __restrict__ gub2,
     const float* __restrict__ jxW1, const float* __restrict__ jxb1,
     const float* __restrict__ jxW2, const float* __restrict__ jxb2) {
    extern __shared__ float sm[];
    int t = blockIdx.y, tid = threadIdx.x;

    if (t < NSTEP) {
        cp4s(sm + SN_GW,        guW1 + t * 192,  192,  tid);
        cp4s(sm + SN_GW + 192,  gub1 + t * 64,   64,   tid);
        cp4s(sm + SN_GW + 256,  guW2 + t * 4096, 4096, tid);
        cp4s(sm + SN_GW + 4352, gub2 + t * 64,   64,   tid);
        cp4s(sm + SN_JW,        jxW1 + t * 192,  192,  tid);
        cp4s(sm + SN_JW + 192,  jxb1 + t * 64,   64,   tid);
        cp4s(sm + SN_JW + 256,  jxW2 + t * 4096, 4096, tid);
        cp4s(sm + SN_JW + 4352, jxb2 + t * 64,   64,   tid);
        const float* wsrc = g_W3Eg + (size_t)t * RR * 192;
        for (int idx = tid; idx < RR * 192; idx += 256) {
            int r = idx / 192, c = idx - r * 192;
            sm[SN_E + c * 41 + r] = wsrc[idx];
        }
        const float* bsrc = g_b3Eg + t * RR * 3;
        for (int idx = tid; idx < RR * 3; idx += 256) {
            int r = idx / 3, o = idx - r * 3;
            sm[SN_B3E + o * 41 + r] = bsrc[idx];
        }
    } else {
        cp4s(sm + SN_GW, uW1, 192, tid);
        cp4s(sm + SN_GW + 192, ub1, 64, tid);
        cp4s(sm + SN_GW + 256, uW2, 4096, tid);
        cp4s(sm + SN_GW + 4352, ub2, 64, tid);
        for (int idx = tid; idx < RR * 64; idx += 256) {
            int r = idx >> 6, j = idx & 63;
            sm[SN_E + j * 41 + r] = g_W3Eu[idx];
        }
        for (int idx = tid; idx < RR; idx += 256) sm[SN_B3E + idx] = g_b3Eu[idx];
    }
    __syncthreads();

    float h1[64];

    if (t < NSTEP) {
#pragma unroll 1
        for (int k = 0; k < 4; k++) {
            int i = blockIdx.x * 1024 + k * 256 + tid;
            float4 av = g_A[t * BB + i];
            float4 mv = g_M[t * BB + i];
            int bits = __float_as_int(mv.w);
            int ridx = bits & 0xFF;
            int n = ridx * 81 + (bits >> 8);
            const float* crow = g_C + ((size_t)t * NPAD + n) * CROW;

            // ---- g-net ----
            layer1(sm + SN_GW, av.x, av.y, av.z, h1);
            float gu0 = sm[SN_B3E + ridx];
            float gu1 = sm[SN_B3E + 41 + ridx];
            float gu2 = sm[SN_B3E + 82 + ridx];
            const float* W2 = sm + SN_GW + 256;
            const float* b2 = sm + SN_GW + 4352;
#pragma unroll 1
            for (int c = 0; c < 8; c++) {
                float4 ba = *(const float4*)(b2 + c * 8);
                float4 bbv = *(const float4*)(b2 + c * 8 + 4);
                float a0 = ba.x, a1 = ba.y, a2 = ba.z, a3 = ba.w;
                float a4 = bbv.x, a5 = bbv.y, a6 = bbv.z, a7 = bbv.w;
#pragma unroll
                for (int j = 0; j < 64; j++) {
                    float hj = h1[j];
                    float4 w0 = *(const float4*)(W2 + j * 64 + c * 8);
                    float4 w1 = *(const float4*)(W2 + j * 64 + c * 8 + 4);
                    a0 = fmaf(hj, w0.x, a0); a1 = fmaf(hj, w0.y, a1);
                    a2 = fmaf(hj, w0.z, a2); a3 = fmaf(hj, w0.w, a3);
                    a4 = fmaf(hj, w1.x, a4); a5 = fmaf(hj, w1.y, a5);
                    a6 = fmaf(hj, w1.z, a6); a7 = fmaf(hj, w1.w, a7);
                }
                float hh[8] = {tanh_fast(a0), tanh_fast(a1), tanh_fast(a2), tanh_fast(a3),
                               tanh_fast(a4), tanh_fast(a5), tanh_fast(a6), tanh_fast(a7)};
#pragma unroll
                for (int q = 0; q < 8; q++) {
                    const float* e = sm + SN_E + ((c * 8 + q) * 3) * 41 + ridx;
                    gu0 = fmaf(hh[q], e[0], gu0);
                    gu1 = fmaf(hh[q], e[41], gu1);
                    gu2 = fmaf(hh[q], e[82], gu2);
                }
            }

            // ---- j-net ----
            layer1(sm + SN_JW, av.x, av.y, av.z, h1);
            float jmp = crow[64];   // c0
            const float4* crow4 = (const float4*)crow;
            float4 ca = crow4[0], cb = crow4[1];
            const float* jW2 = sm + SN_JW + 256;
            const float* jb2 = sm + SN_JW + 4352;
#pragma unroll 1
            for (int c = 0; c < 8; c++) {
                float4 na, nb;
                if (c < 7) { na = crow4[2 * c + 2]; nb = crow4[2 * c + 3]; }
                float4 ba = *(const float4*)(jb2 + c * 8);
                float4 bbv = *(const float4*)(jb2 + c * 8 + 4);
                float a0 = ba.x, a1 = ba.y, a2 = ba.z, a3 = ba.w;
                float a4 = bbv.x, a5 = bbv.y, a6 = bbv.z, a7 = bbv.w;
#pragma unroll
                for (int j = 0; j < 64; j++) {
                    float hj = h1[j];
                    float4 w0 = *(const float4*)(jW2 + j * 64 + c * 8);
                    float4 w1 = *(const float4*)(jW2 + j * 64 + c * 8 + 4);
                    a0 = fmaf(hj, w0.x, a0); a1 = fmaf(hj, w0.y, a1);
                    a2 = fmaf(hj, w0.z, a2); a3 = fmaf(hj, w0.w, a3);
                    a4 = fmaf(hj, w1.x, a4); a5 = fmaf(hj, w1.y, a5);
                    a6 = fmaf(hj, w1.z, a6); a7 = fmaf(hj, w1.w, a7);
                }
                jmp = fmaf(tanh_fast(a0), ca.x, jmp);
                jmp = fmaf(tanh_fast(a1), ca.y, jmp);
                jmp = fmaf(tanh_fast(a2), ca.z, jmp);
                jmp = fmaf(tanh_fast(a3), ca.w, jmp);
                jmp = fmaf(tanh_fast(a4), cb.x, jmp);
                jmp = fmaf(tanh_fast(a5), cb.y, jmp);
                jmp = fmaf(tanh_fast(a6), cb.z, jmp);
                jmp = fmaf(tanh_fast(a7), cb.w, jmp);
                ca = na; cb = nb;
            }

            g_part[t * BB + i] = gu0 * mv.x + gu1 * mv.y + gu2 * mv.z + av.w * jmp;
        }
    } else {
        // u0 slice
#pragma unroll 1
        for (int k = 0; k < 4; k++) {
            int i = blockIdx.x * 1024 + k * 256 + tid;
            float x0 = xt0[i * 3 + 0], x1 = xt0[i * 3 + 1], x2 = xt0[i * 3 + 2];
            int ridx = rt0[i] - RMIN;
            layer1(sm + SN_GW, x0, x1, x2, h1);
            float u = sm[SN_B3E + ridx];
            const float* W2 = sm + SN_GW + 256;
            const float* b2 = sm + SN_GW + 4352;
#pragma unroll 1
            for (int c = 0; c < 8; c++) {
                float4 ba = *(const float4*)(b2 + c * 8);
                float4 bbv = *(const float4*)(b2 + c * 8 + 4);
                float a0 = ba.x, a1 = ba.y, a2 = ba.z, a3 = ba.w;
                float a4 = bbv.x, a5 = bbv.y, a6 = bbv.z, a7 = bbv.w;
#pragma unroll
                for (int j = 0; j < 64; j++) {
                    float hj = h1[j];
                    float4 w0 = *(const float4*)(W2 + j * 64 + c * 8);
                    float4 w1 = *(const float4*)(W2 + j * 64 + c * 8 + 4);
                    a0 = fmaf(hj, w0.x, a0); a1 = fmaf(hj, w0.y, a1);
                    a2 = fmaf(hj, w0.z, a2); a3 = fmaf(hj, w0.w, a3);
                    a4 = fmaf(hj, w1.x, a4); a5 = fmaf(hj, w1.y, a5);
                    a6 = fmaf(hj, w1.z, a6); a7 = fmaf(hj, w1.w, a7);
                }
                const float* e = sm + SN_E + (c * 8) * 41 + ridx;
                u = fmaf(tanh_fast(a0), e[0 * 41], u);
                u = fmaf(tanh_fast(a1), e[1 * 41], u);
                u = fmaf(tanh_fast(a2), e[2 * 41], u);
                u = fmaf(tanh_fast(a3), e[3 * 41], u);
                u = fmaf(tanh_fast(a4), e[4 * 41], u);
                u = fmaf(tanh_fast(a5), e[5 * 41], u);
                u = fmaf(tanh_fast(a6), e[6 * 41], u);
                u = fmaf(tanh_fast(a7), e[7 * 41], u);
            }
            g_part[NSTEP * BB + i] = u;
        }
    }
}

// ---------------- reduction ----------------
__global__ void __launch_bounds__(256)
k_reduce(float* __restrict__ out) {
    int i = blockIdx.x * 256 + threadIdx.x;
    float s = g_part[NSTEP * BB + i];
#pragma unroll 1
    for (int t = 0; t < NSTEP; t++) s += g_part[t * BB + i];
    out[i] = s;
}

// ---------------- launcher ----------------
extern "C" void kernel_launch(void* const* d_in, const int* in_sizes, int n_in,
                              void* d_out, int out_size) {
    const int*   rt0    = (const int*)d_in[1];
    const float* xt0    = (const float*)d_in[2];
    const float* dBt    = (const float*)d_in[3];
    const float* u_jump = (const float*)d_in[4];
    const float* u_size = (const float*)d_in[5];
    const float* u_mc   = (const float*)d_in[6];
    const float* uW1 = (const float*)d_in[7];
    const float* ub1 = (const float*)d_in[8];
    const float* uW2 = (const float*)d_in[9];
    const float* ub2 = (const float*)d_in[10];
    const float* uW3 = (const float*)d_in[11];
    const float* ub3 = (const float*)d_in[12];
    const float* uE  = (const float*)d_in[13];
    const float* guW1 = (const float*)d_in[14];
    const float* gub1 = (const float*)d_in[15];
    const float* guW2 = (const float*)d_in[16];
    const float* gub2 = (const float*)d_in[17];
    const float* guW3 = (const float*)d_in[18];
    const float* gub3 = (const float*)d_in[19];
    const float* guE  = (const float*)d_in[20];
    const float* jxW1 = (const float*)d_in[21];
    const float* jxb1 = (const float*)d_in[22];
    const float* jxW2 = (const float*)d_in[23];
    const float* jxb2 = (const float*)d_in[24];
    const float* jxW3 = (const float*)d_in[25];
    const float* jxb3 = (const float*)d_in[26];
    const float* jump_r = (const float*)d_in[27];
    const float* jump_l = (const float*)d_in[28];
    float* out = (float*)d_out;

    cudaFuncSetAttribute(k_build_w3e, cudaFuncAttributeMaxDynamicSharedMemorySize,
                         SMEM_W3E_FLOATS * 4);
    cudaFuncSetAttribute(k_build_C, cudaFuncAttributeMaxDynamicSharedMemorySize,
                         SMEM_C_FLOATS * 4);
    cudaFuncSetAttribute(k_nn, cudaFuncAttributeMaxDynamicSharedMemorySize,
                         SN_TOT * 4);

    k_tables<<<1, 64>>>();
    k_mc_hist<<<(MCN * RR + 255) / 256, 256>>>(u_mc);
    k_mc_combine<<<(RR * PP + 127) / 128, 128>>>(jump_l);
    k_build_w3e<<<NSTEP + 1, 256, SMEM_W3E_FLOATS * 4>>>(guW3, gub3, guE, uW3, ub3, uE);
    k_build_C<<<dim3(NBLK, NSTEP), 256, SMEM_C_FLOATS * 4>>>(jxW3, jxb3, jump_r, jump_l);
    k_geom<<<BB / 256, 256>>>(rt0, xt0, dBt, u_jump, u_size, out);
    k_nn<<<dim3(16, NSTEP + 1), 256, SN_TOT * 4>>>(
        xt0, rt0, uW1, ub1, uW2, ub2,
        guW1, gub1, guW2, gub2,
        jxW1, jxb1, jxW2, jxb2);
    k_reduce<<<BB / 256, 256>>>(out);
    (void)in_sizes; (void)n_in; (void)out_size;
}

// round 6
// speedup vs baseline: 4.4069x; 1.4206x over previous
#include <cuda_runtime.h>
#include <math.h>

#define RMIN 10
#define GAP  40
#define RR   41
#define PP   128
#define NSTEP 32
#define BB   16384
#define MCN  10000
#define DT_F 0.03125f
#define PI_F 3.14159265358979323846f
#define NPAD 3328       // 41*81 = 3321 padded
#define NBLK 52
#define CROW 68         // 64 coeffs + c0 + 3 pad
#define NCH  9          // k_nn sample chunks (9*33 = 297 blocks ~ 1 wave)

// ---------------- device scratch ----------------
__device__ float g_jm[RR * 80];
__device__ float g_cr[RR];
__device__ float g_cfr[RR];
__device__ int   g_hist[RR * 80];
__device__ float g_mcjump[RR * PP];
__device__ float g_W3Eu[RR * 64];
__device__ float g_b3Eu[RR];
__device__ float g_W3Eg[NSTEP * RR * 192];
__device__ float g_b3Eg[NSTEP * RR * 3];
__device__ float g_C[(size_t)NSTEP * NPAD * CROW];   // ~29 MB
__device__ float4 g_A[NSTEP * BB];                   // xi0,xi1,xi2, ef
__device__ float4 g_M[NSTEP * BB];                   // m0,m1,m2, bits(ridx|d<<8)
__device__ float  g_part[(NSTEP + 1) * BB];

// upper bound on non-decreasing 80-row: #(row[j] <= u)
__device__ __forceinline__ int ubound80(const float* __restrict__ row, float u) {
    int lo = 0, hi = 80;
    while (lo < hi) {
        int mid = (lo + hi) >> 1;
        if (row[mid] <= u) lo = mid + 1; else hi = mid;
    }
    return lo;
}

// ---------------- tables (+ hist zero) ----------------
__global__ void k_tables() {
    int tid = threadIdx.x;
    for (int i = tid; i < RR * 80; i += 64) g_hist[i] = 0;
    int r = tid;
    if (r >= RR) return;
    float cum = 0.f, slam = 0.f, smu = 0.f;
    for (int k = 1; k <= GAP; k++) {
        float kk = (float)k;
        float lam = ((r + RMIN + k) <= RMIN + GAP) ? 1.0f / (kk * kk) : 0.0f;
        slam += lam; cum += lam;
        g_jm[r * 80 + (k - 1)] = cum;
    }
    for (int k = 1; k <= GAP; k++) {
        float kk = (float)k;
        float mu = ((r + RMIN - k) >= RMIN) ? 1.0f / (kk * kk) : 0.0f;
        smu += mu; cum += mu;
        g_jm[r * 80 + GAP + (k - 1)] = cum;
    }
    g_cr[r] = cum;
    g_cfr[r] = slam + smu - cum;
    for (int j = 0; j < 80; j++) g_jm[r * 80 + j] /= cum;
}

__global__ void k_mc_hist(const float* __restrict__ u_mc) {
    int i = blockIdx.x * blockDim.x + threadIdx.x;
    if (i >= MCN * RR) return;
    int r = i % RR;
    int ind = ubound80(&g_jm[r * 80], u_mc[i]);
    atomicAdd(&g_hist[r * 80 + ind], 1);
}

__global__ void k_mc_combine(const float* __restrict__ jump_l) {
    int idx = blockIdx.x * blockDim.x + threadIdx.x;
    if (idx >= RR * PP) return;
    int r = idx / PP, p = idx % PP;
    float s = 0.f;
    for (int b = 0; b < 80; b++) {
        int c = g_hist[r * 80 + b];
        if (c) s += (float)c * jump_l[b * PP + p];
    }
    g_mcjump[idx] = s * (1.0f / (float)MCN) * g_cr[r];
}

// ---------------- W3E build: one CTA per (r, t);  t=NSTEP -> u-net ----------------
__global__ void __launch_bounds__(192, 4)
k_build_w3e(const float* __restrict__ guW3, const float* __restrict__ gub3,
            const float* __restrict__ guE,
            const float* __restrict__ uW3, const float* __restrict__ ub3,
            const float* __restrict__ uE) {
    __shared__ float sW[64 * 129];
    __shared__ float sE[384];
    int r = blockIdx.x, t = blockIdx.y, tid = threadIdx.x;
    if (t < NSTEP) {
        for (int idx = tid; idx < 8192; idx += 192) {
            int j = idx >> 7, p = idx & 127;
            sW[j * 129 + p] = guW3[(size_t)t * 8192 + idx];
        }
        for (int idx = tid; idx < 384; idx += 192)
            sE[idx] = guE[((size_t)t * RR + r) * 384 + idx];
        __syncthreads();
        int j = tid / 3, o = tid - j * 3;
        const float* w = sW + j * 129;
        const float* e = sE + o;
        float acc = 0.f;
#pragma unroll 8
        for (int p = 0; p < 128; p++) acc = fmaf(w[p], e[p * 3], acc);
        g_W3Eg[((size_t)t * RR + r) * 192 + tid] = acc;
        if (tid < 3) {
            const float* b = gub3 + t * 128;
            float a = 0.f;
#pragma unroll 8
            for (int p = 0; p < 128; p++) a = fmaf(b[p], sE[p * 3 + tid], a);
            g_b3Eg[(t * RR + r) * 3 + tid] = a;
        }
    } else {
        for (int idx = tid; idx < 8192; idx += 192) {
            int j = idx >> 7, p = idx & 127;
            sW[j * 129 + p] = uW3[idx];
        }
        for (int idx = tid; idx < 128; idx += 192) sE[idx] = uE[r * 128 + idx];
        __syncthreads();
        if (tid < 64) {
            const float* w = sW + tid * 129;
            float acc = 0.f;
#pragma unroll 8
            for (int p = 0; p < 128; p++) acc = fmaf(w[p], sE[p], acc);
            g_W3Eu[r * 64 + tid] = acc;
        }
        if (tid == 64) {
            float acc = 0.f;
#pragma unroll 8
            for (int p = 0; p < 128; p++) acc = fmaf(ub3[p], sE[p], acc);
            g_b3Eu[r] = acc;
        }
    }
}

// ---------------- C table build (transposed [p][.] staging) ----------------
#define CPAD 68
#define SMEM_C_FLOATS (2 * 128 * CPAD)
__global__ void __launch_bounds__(256, 1)
k_build_C(const float* __restrict__ jxW3, const float* __restrict__ jxb3,
          const float* __restrict__ jump_r, const float* __restrict__ jump_l) {
    extern __shared__ float smc[];
    float* smA = smc;                 // [128][68]: smA[p][j]
    float* smB = smc + 128 * CPAD;    // [128][68]: smB[p][n]
    int nblk = blockIdx.x, t = blockIdx.y, tid = threadIdx.x;

    for (int idx = tid; idx < 8192; idx += 256) {
        int j = idx >> 7, p = idx & 127;
        smA[p * CPAD + j] = jxW3[(size_t)t * 8192 + idx];
    }
    for (int idx = tid; idx < 8192; idx += 256) {
        int n = idx >> 7, p = idx & 127;
        int n_g = nblk * 64 + n;
        float b = 0.f;
        if (n_g < RR * 81) {
            int r = n_g / 81, d = n_g - r * 81;
            float jl = 0.f;
            if (d > 40)      jl = jump_l[(d - 41) * PP + p];
            else if (d < 40) jl = jump_l[(79 - d) * PP + p];
            b = jump_r[r * PP + p] * (jl - g_mcjump[r * PP + p] * DT_F);
        }
        smB[p * CPAD + n] = b;
    }
    __syncthreads();

    int tx = tid & 15, ty = tid >> 4;
    float acc[16];
#pragma unroll
    for (int q = 0; q < 16; q++) acc[q] = 0.f;
#pragma unroll 4
    for (int p = 0; p < 128; p++) {
        float4 av = *(const float4*)(smA + p * CPAD + ty * 4);
        float4 bv = *(const float4*)(smB + p * CPAD + tx * 4);
        acc[0]  = fmaf(av.x, bv.x, acc[0]);  acc[1]  = fmaf(av.x, bv.y, acc[1]);
        acc[2]  = fmaf(av.x, bv.z, acc[2]);  acc[3]  = fmaf(av.x, bv.w, acc[3]);
        acc[4]  = fmaf(av.y, bv.x, acc[4]);  acc[5]  = fmaf(av.y, bv.y, acc[5]);
        acc[6]  = fmaf(av.y, bv.z, acc[6]);  acc[7]  = fmaf(av.y, bv.w, acc[7]);
        acc[8]  = fmaf(av.z, bv.x, acc[8]);  acc[9]  = fmaf(av.z, bv.y, acc[9]);
        acc[10] = fmaf(av.z, bv.z, acc[10]); acc[11] = fmaf(av.z, bv.w, acc[11]);
        acc[12] = fmaf(av.w, bv.x, acc[12]); acc[13] = fmaf(av.w, bv.y, acc[13]);
        acc[14] = fmaf(av.w, bv.z, acc[14]); acc[15] = fmaf(av.w, bv.w, acc[15]);
    }
#pragma unroll
    for (int ii = 0; ii < 4; ii++) {
        int j = ty * 4 + ii;
#pragma unroll
        for (int nn = 0; nn < 4; nn++) {
            int n_g = nblk * 64 + tx * 4 + nn;
            g_C[((size_t)t * NPAD + n_g) * CROW + j] = acc[ii * 4 + nn];
        }
    }
    if (tid < 64) {
        int n_g = nblk * 64 + tid;
        const float* b3 = jxb3 + t * 128;
        float c0 = 0.f;
#pragma unroll 4
        for (int p = 0; p < 128; p++) c0 = fmaf(b3[p], smB[p * CPAD + tid], c0);
        size_t base = ((size_t)t * NPAD + n_g) * CROW;
        g_C[base + 64] = c0;
        g_C[base + 65] = 0.f; g_C[base + 66] = 0.f; g_C[base + 67] = 0.f;
    }
}

// ---------------- geometry pass: trajectory only, NN-free ----------------
__global__ void __launch_bounds__(256)
k_geom(const int* __restrict__ rt0, const float* __restrict__ xt0,
       const float* __restrict__ dBt, const float* __restrict__ u_jump,
       const float* __restrict__ u_size, float* __restrict__ out) {
    __shared__ float sJM[RR * 80];
    __shared__ float sCR[RR];
    __shared__ float sCF[RR];
    int tid = threadIdx.x;
    for (int idx = tid; idx < RR * 80; idx += 256) sJM[idx] = g_jm[idx];
    for (int idx = tid; idx < RR; idx += 256) {
        sCR[idx] = g_cr[idx];
        sCF[idx] = g_cfr[idx];
    }
    __syncthreads();

    int i = blockIdx.x * 256 + tid;
    const float sqDT = 0.17677669529663688985f;   // sqrt(1/32)
    const float sq2D = 1.41421356237309504880f;   // sqrt(2)
    int rt = rt0[i];
    float x0 = xt0[i * 3 + 0], x1 = xt0[i * 3 + 1], x2 = xt0[i * 3 + 2];
    float xi0 = x0, xi1 = x1, xi2 = x2;
    float sgn = 1.f, fun = 0.f;

#pragma unroll 1
    for (int t = 0; t < NSTEP; t++) {
        int ridx = rt - RMIN;
        float uj = u_jump[t * BB + i];
        int drt = 0;
        if (uj < sCR[ridx] * DT_F) {
            int ind = ubound80(sJM + ridx * 80, u_size[t * BB + i]);
            drt = (ind < GAP) ? (ind + 1) : -(ind - GAP + 1);
        }

        float rn = sqrtf(x0 * x0 + x1 * x1 + x2 * x2);
        float cz = fminf(fmaxf(x2 / rn, -1.0f), 1.0f);
        float theta = acosf(cz) - 0.5f * PI_F;
        float phi = atan2f(x1, x0);
        float st, ct, sp, cpv;
        sincosf(theta, &st, &ct);
        sincosf(phi, &sp, &cpv);
        float T00 = cpv * ct, T01 = -sp,  T02 = cpv * st;
        float T10 = sp * ct,  T11 = cpv,  T12 = sp * st;
        float T20 = -st,      T22 = ct;

        float2 db = ((const float2*)dBt)[t * BB + i];
        float dB0 = db.x * sqDT, dB1 = db.y * sqDT;
        float rtf = (float)rt;
        float c1 = sq2D / rtf;
        float ef = expf(-fun);

        float m0 = ef * c1 * (T01 * dB1 - T02 * dB0);
        float m1 = ef * c1 * (T11 * dB1 - T12 * dB0);
        float m2 = -ef * c1 * sgn * T22 * dB0;
        float4 av; av.x = xi0; av.y = xi1; av.z = xi2; av.w = ef;
        g_A[t * BB + i] = av;
        float4 mv; mv.x = m0; mv.y = m1; mv.z = m2;
        mv.w = __int_as_float(ridx | ((drt + 40) << 8));
        g_M[t * BB + i] = mv;

        fun += sCF[ridx] * DT_F;

        float dX20 = c1 * dB0, dX21 = c1 * dB1;
        float th_d = dX20 + 0.5f * PI_F;
        float sth, cth, sph, cph;
        sincosf(th_d, &sth, &cth);
        sincosf(dX21, &sph, &cph);
        float d30 = sth * cph - 1.0f;
        float d31 = sth * sph;
        float d32 = cth;
        float dX0 = T00 * d30 + T01 * d31 + T02 * d32;
        float dX1 = T10 * d30 + T11 * d31 + T12 * d32;
        float dX2 = T20 * d30 + T22 * d32;     // T21 = 0
        x0 += dX0; x1 += dX1; x2 += dX2;
        xi0 += dX0; xi1 += dX1; xi2 += sgn * dX2;
        rt += drt;
        if (xi2 < 0.f) { xi2 = -xi2; sgn = -sgn; }
    }

    float ef = expf(-fun);
    out[BB + i] = (xi0 * xi0 + xi1 * xi1 + xi2 * xi2) / (float)rt * ef;
}

// ---------------- helpers ----------------
__device__ __forceinline__ void cp4s(float* dst, const float* __restrict__ src,
                                     int nfl, int tid) {
    const float4* s = (const float4*)src;
    float4* d = (float4*)dst;
    int n4 = nfl >> 2;
    for (int i = tid; i < n4; i += 256) d[i] = s[i];
}

// tanh = 1 - 2/(1+e^{2x}); clamp-free (inf -> 1, underflow -> -1), 5 instrs, 2 MUFU
__device__ __forceinline__ float tanh_fast(float x) {
    float e = __expf(2.0f * x);
    float r = __fdividef(1.0f, e + 1.0f);
    return fmaf(-2.0f, r, 1.0f);
}

// layer1: x(3) -> tanh(64); weights W1 @0 [3][64], b1 @192
__device__ __forceinline__ void layer1(const float* __restrict__ W,
                                       float x0, float x1, float x2, float* h1) {
#pragma unroll
    for (int j = 0; j < 64; j += 4) {
        float4 wa = *(const float4*)(W + j);
        float4 wb = *(const float4*)(W + 64 + j);
        float4 wc = *(const float4*)(W + 128 + j);
        float4 bb = *(const float4*)(W + 192 + j);
        h1[j + 0] = tanh_fast(fmaf(x0, wa.x, fmaf(x1, wb.x, fmaf(x2, wc.x, bb.x))));
        h1[j + 1] = tanh_fast(fmaf(x0, wa.y, fmaf(x1, wb.y, fmaf(x2, wc.y, bb.y))));
        h1[j + 2] = tanh_fast(fmaf(x0, wa.z, fmaf(x1, wb.z, fmaf(x2, wc.z, bb.z))));
        h1[j + 3] = tanh_fast(fmaf(x0, wa.w, fmaf(x1, wb.w, fmaf(x2, wc.w, bb.w))));
    }
}

// ---------------- NN kernel: grid (NCH chunks, t) ----------------
// smem: gW 4416 | jW 4416 | E 7872 | B3E 128  = 16832 floats
#define SN_GW   0
#define SN_JW   4416
#define SN_E    8832
#define SN_B3E  16704
#define SN_TOT  16832
__global__ void __launch_bounds__(256, 2)
k_nn(const float* __restrict__ xt0, const int* __restrict__ rt0,
     const float* __restrict__ uW1, const float* __restrict__ ub1,
     const float* __restrict__ uW2, const float* __restrict__ ub2,
     const float* __restrict__ guW1, const float* __restrict__ gub1,
     const float* __restrict__ guW2, const float* __restrict__ gub2,
     const float* __restrict__ jxW1, const float* __restrict__ jxb1,
     const float* __restrict__ jxW2, const float* __restrict__ jxb2) {
    extern __shared__ float sm[];
    int t = blockIdx.y, tid = threadIdx.x;

    if (t < NSTEP) {
        cp4s(sm + SN_GW,        guW1 + t * 192,  192,  tid);
        cp4s(sm + SN_GW + 192,  gub1 + t * 64,   64,   tid);
        cp4s(sm + SN_GW + 256,  guW2 + t * 4096, 4096, tid);
        cp4s(sm + SN_GW + 4352, gub2 + t * 64,   64,   tid);
        cp4s(sm + SN_JW,        jxW1 + t * 192,  192,  tid);
        cp4s(sm + SN_JW + 192,  jxb1 + t * 64,   64,   tid);
        cp4s(sm + SN_JW + 256,  jxW2 + t * 4096, 4096, tid);
        cp4s(sm + SN_JW + 4352, jxb2 + t * 64,   64,   tid);
        const float* wsrc = g_W3Eg + (size_t)t * RR * 192;
        for (int idx = tid; idx < RR * 192; idx += 256) {
            int r = idx / 192, c = idx - r * 192;
            sm[SN_E + c * 41 + r] = wsrc[idx];
        }
        const float* bsrc = g_b3Eg + t * RR * 3;
        for (int idx = tid; idx < RR * 3; idx += 256) {
            int r = idx / 3, o = idx - r * 3;
            sm[SN_B3E + o * 41 + r] = bsrc[idx];
        }
    } else {
        cp4s(sm + SN_GW, uW1, 192, tid);
        cp4s(sm + SN_GW + 192, ub1, 64, tid);
        cp4s(sm + SN_GW + 256, uW2, 4096, tid);
        cp4s(sm + SN_GW + 4352, ub2, 64, tid);
        for (int idx = tid; idx < RR * 64; idx += 256) {
            int r = idx >> 6, j = idx & 63;
            sm[SN_E + j * 41 + r] = g_W3Eu[idx];
        }
        for (int idx = tid; idx < RR; idx += 256) sm[SN_B3E + idx] = g_b3Eu[idx];
    }
    __syncthreads();

    float h1[64];

    if (t < NSTEP) {
#pragma unroll 1
        for (int k = 0; k < 8; k++) {
            int i = blockIdx.x * 256 + k * (NCH * 256) + tid;
            if (i >= BB) break;
            float4 av = g_A[t * BB + i];
            float4 mv = g_M[t * BB + i];
            int bits = __float_as_int(mv.w);
            int ridx = bits & 0xFF;
            int n = ridx * 81 + (bits >> 8);
            const float* crow = g_C + ((size_t)t * NPAD + n) * CROW;

            // ---- g-net ----
            layer1(sm + SN_GW, av.x, av.y, av.z, h1);
            float gu0 = sm[SN_B3E + ridx];
            float gu1 = sm[SN_B3E + 41 + ridx];
            float gu2 = sm[SN_B3E + 82 + ridx];
            const float* W2 = sm + SN_GW + 256;
            const float* b2 = sm + SN_GW + 4352;
#pragma unroll 1
            for (int c = 0; c < 8; c++) {
                float4 ba = *(const float4*)(b2 + c * 8);
                float4 bbv = *(const float4*)(b2 + c * 8 + 4);
                float a0 = ba.x, a1 = ba.y, a2 = ba.z, a3 = ba.w;
                float a4 = bbv.x, a5 = bbv.y, a6 = bbv.z, a7 = bbv.w;
#pragma unroll
                for (int j = 0; j < 64; j++) {
                    float hj = h1[j];
                    float4 w0 = *(const float4*)(W2 + j * 64 + c * 8);
                    float4 w1 = *(const float4*)(W2 + j * 64 + c * 8 + 4);
                    a0 = fmaf(hj, w0.x, a0); a1 = fmaf(hj, w0.y, a1);
                    a2 = fmaf(hj, w0.z, a2); a3 = fmaf(hj, w0.w, a3);
                    a4 = fmaf(hj, w1.x, a4); a5 = fmaf(hj, w1.y, a5);
                    a6 = fmaf(hj, w1.z, a6); a7 = fmaf(hj, w1.w, a7);
                }
                float hh[8] = {tanh_fast(a0), tanh_fast(a1), tanh_fast(a2), tanh_fast(a3),
                               tanh_fast(a4), tanh_fast(a5), tanh_fast(a6), tanh_fast(a7)};
#pragma unroll
                for (int q = 0; q < 8; q++) {
                    const float* e = sm + SN_E + ((c * 8 + q) * 3) * 41 + ridx;
                    gu0 = fmaf(hh[q], e[0], gu0);
                    gu1 = fmaf(hh[q], e[41], gu1);
                    gu2 = fmaf(hh[q], e[82], gu2);
                }
            }

            // ---- j-net ----
            layer1(sm + SN_JW, av.x, av.y, av.z, h1);
            float jmp = crow[64];   // c0
            const float4* crow4 = (const float4*)crow;
            float4 ca = crow4[0], cb = crow4[1];
            const float* jW2 = sm + SN_JW + 256;
            const float* jb2 = sm + SN_JW + 4352;
#pragma unroll 1
            for (int c = 0; c < 8; c++) {
                float4 na = ca, nb = cb;
                if (c < 7) { na = crow4[2 * c + 2]; nb = crow4[2 * c + 3]; }
                float4 ba = *(const float4*)(jb2 + c * 8);
                float4 bbv = *(const float4*)(jb2 + c * 8 + 4);
                float a0 = ba.x, a1 = ba.y, a2 = ba.z, a3 = ba.w;
                float a4 = bbv.x, a5 = bbv.y, a6 = bbv.z, a7 = bbv.w;
#pragma unroll
                for (int j = 0; j < 64; j++) {
                    float hj = h1[j];
                    float4 w0 = *(const float4*)(jW2 + j * 64 + c * 8);
                    float4 w1 = *(const float4*)(jW2 + j * 64 + c * 8 + 4);
                    a0 = fmaf(hj, w0.x, a0); a1 = fmaf(hj, w0.y, a1);
                    a2 = fmaf(hj, w0.z, a2); a3 = fmaf(hj, w0.w, a3);
                    a4 = fmaf(hj, w1.x, a4); a5 = fmaf(hj, w1.y, a5);
                    a6 = fmaf(hj, w1.z, a6); a7 = fmaf(hj, w1.w, a7);
                }
                jmp = fmaf(tanh_fast(a0), ca.x, jmp);
                jmp = fmaf(tanh_fast(a1), ca.y, jmp);
                jmp = fmaf(tanh_fast(a2), ca.z, jmp);
                jmp = fmaf(tanh_fast(a3), ca.w, jmp);
                jmp = fmaf(tanh_fast(a4), cb.x, jmp);
                jmp = fmaf(tanh_fast(a5), cb.y, jmp);
                jmp = fmaf(tanh_fast(a6), cb.z, jmp);
                jmp = fmaf(tanh_fast(a7), cb.w, jmp);
                ca = na; cb = nb;
            }

            g_part[t * BB + i] = gu0 * mv.x + gu1 * mv.y + gu2 * mv.z + av.w * jmp;
        }
    } else {
        // u0 slice
#pragma unroll 1
        for (int k = 0; k < 8; k++) {
            int i = blockIdx.x * 256 + k * (NCH * 256) + tid;
            if (i >= BB) break;
            float x0 = xt0[i * 3 + 0], x1 = xt0[i * 3 + 1], x2 = xt0[i * 3 + 2];
            int ridx = rt0[i] - RMIN;
            layer1(sm + SN_GW, x0, x1, x2, h1);
            float u = sm[SN_B3E + ridx];
            const float* W2 = sm + SN_GW + 256;
            const float* b2 = sm + SN_GW + 4352;
#pragma unroll 1
            for (int c = 0; c < 8; c++) {
                float4 ba = *(const float4*)(b2 + c * 8);
                float4 bbv = *(const float4*)(b2 + c * 8 + 4);
                float a0 = ba.x, a1 = ba.y, a2 = ba.z, a3 = ba.w;
                float a4 = bbv.x, a5 = bbv.y, a6 = bbv.z, a7 = bbv.w;
#pragma unroll
                for (int j = 0; j < 64; j++) {
                    float hj = h1[j];
                    float4 w0 = *(const float4*)(W2 + j * 64 + c * 8);
                    float4 w1 = *(const float4*)(W2 + j * 64 + c * 8 + 4);
                    a0 = fmaf(hj, w0.x, a0); a1 = fmaf(hj, w0.y, a1);
                    a2 = fmaf(hj, w0.z, a2); a3 = fmaf(hj, w0.w, a3);
                    a4 = fmaf(hj, w1.x, a4); a5 = fmaf(hj, w1.y, a5);
                    a6 = fmaf(hj, w1.z, a6); a7 = fmaf(hj, w1.w, a7);
                }
                const float* e = sm + SN_E + (c * 8) * 41 + ridx;
                u = fmaf(tanh_fast(a0), e[0 * 41], u);
                u = fmaf(tanh_fast(a1), e[1 * 41], u);
                u = fmaf(tanh_fast(a2), e[2 * 41], u);
                u = fmaf(tanh_fast(a3), e[3 * 41], u);
                u = fmaf(tanh_fast(a4), e[4 * 41], u);
                u = fmaf(tanh_fast(a5), e[5 * 41], u);
                u = fmaf(tanh_fast(a6), e[6 * 41], u);
                u = fmaf(tanh_fast(a7), e[7 * 41], u);
            }
            g_part[NSTEP * BB + i] = u;
        }
    }
}

// ---------------- reduction ----------------
__global__ void __launch_bounds__(256)
k_reduce(float* __restrict__ out) {
    int i = blockIdx.x * 256 + threadIdx.x;
    float s = g_part[NSTEP * BB + i];
#pragma unroll 1
    for (int t = 0; t < NSTEP; t++) s += g_part[t * BB + i];
    out[i] = s;
}

// ---------------- launcher ----------------
extern "C" void kernel_launch(void* const* d_in, const int* in_sizes, int n_in,
                              void* d_out, int out_size) {
    const int*   rt0    = (const int*)d_in[1];
    const float* xt0    = (const float*)d_in[2];
    const float* dBt    = (const float*)d_in[3];
    const float* u_jump = (const float*)d_in[4];
    const float* u_size = (const float*)d_in[5];
    const float* u_mc   = (const float*)d_in[6];
    const float* uW1 = (const float*)d_in[7];
    const float* ub1 = (const float*)d_in[8];
    const float* uW2 = (const float*)d_in[9];
    const float* ub2 = (const float*)d_in[10];
    const float* uW3 = (const float*)d_in[11];
    const float* ub3 = (const float*)d_in[12];
    const float* uE  = (const float*)d_in[13];
    const float* guW1 = (const float*)d_in[14];
    const float* gub1 = (const float*)d_in[15];
    const float* guW2 = (const float*)d_in[16];
    const float* gub2 = (const float*)d_in[17];
    const float* guW3 = (const float*)d_in[18];
    const float* gub3 = (const float*)d_in[19];
    const float* guE  = (const float*)d_in[20];
    const float* jxW1 = (const float*)d_in[21];
    const float* jxb1 = (const float*)d_in[22];
    const float* jxW2 = (const float*)d_in[23];
    const float* jxb2 = (const float*)d_in[24];
    const float* jxW3 = (const float*)d_in[25];
    const float* jxb3 = (const float*)d_in[26];
    const float* jump_r = (const float*)d_in[27];
    const float* jump_l = (const float*)d_in[28];
    float* out = (float*)d_out;

    cudaFuncSetAttribute(k_build_C, cudaFuncAttributeMaxDynamicSharedMemorySize,
                         SMEM_C_FLOATS * 4);
    cudaFuncSetAttribute(k_nn, cudaFuncAttributeMaxDynamicSharedMemorySize,
                         SN_TOT * 4);

    k_tables<<<1, 64>>>();
    k_mc_hist<<<(MCN * RR + 255) / 256, 256>>>(u_mc);
    k_mc_combine<<<(RR * PP + 127) / 128, 128>>>(jump_l);
    k_build_w3e<<<dim3(RR, NSTEP + 1), 192>>>(guW3, gub3, guE, uW3, ub3, uE);
    k_build_C<<<dim3(NBLK, NSTEP), 256, SMEM_C_FLOATS * 4>>>(jxW3, jxb3, jump_r, jump_l);
    k_geom<<<BB / 256, 256>>>(rt0, xt0, dBt, u_jump, u_size, out);
    k_nn<<<dim3(NCH, NSTEP + 1), 256, SN_TOT * 4>>>(
        xt0, rt0, uW1, ub1, uW2, ub2,
        guW1, gub1, guW2, gub2,
        jxW1, jxb1, jxW2, jxb2);
    k_reduce<<<BB / 256, 256>>>(out);
    (void)in_sizes; (void)n_in; (void)out_size;
}

// round 7
// speedup vs baseline: 4.7666x; 1.0816x over previous
#include <cuda_runtime.h>
#include <math.h>

#define RMIN 10
#define GAP  40
#define RR   41
#define PP   128
#define NSTEP 32
#define BB   16384
#define MCN  10000
#define DT_F 0.03125f
#define PI_F 3.14159265358979323846f
#define NPAD 3328       // 41*81 = 3321 padded
#define NBLK 52
#define CROW 68         // 64 coeffs + c0 + 3 pad
#define NCH  9          // k_nn sample chunks (9*33 = 297 blocks ~ 1 wave)

typedef unsigned long long ull;

// ---------------- f32x2 packed helpers ----------------
__device__ __forceinline__ ull pack2(float lo, float hi) {
    ull r;
    asm("mov.b64 %0, {%1, %2};" : "=l"(r) : "f"(lo), "f"(hi));
    return r;
}
__device__ __forceinline__ ull fma2(ull a, ull b, ull c) {
    ull d;
    asm("fma.rn.f32x2 %0, %1, %2, %3;" : "=l"(d) : "l"(a), "l"(b), "l"(c));
    return d;
}
__device__ __forceinline__ float2 unpk(ull v) {
    float2 f;
    asm("mov.b64 {%0, %1}, %2;" : "=f"(f.x), "=f"(f.y) : "l"(v));
    return f;
}

// ---------------- device scratch ----------------
__device__ float g_jm[RR * 80];
__device__ float g_cr[RR];
__device__ float g_cfr[RR];
__device__ int   g_hist[RR * 80];
__device__ float g_mcjump[RR * PP];
__device__ float g_W3Eu[RR * 64];
__device__ float g_b3Eu[RR];
__device__ float g_W3Eg[NSTEP * RR * 192];
__device__ float g_b3Eg[NSTEP * RR * 3];
__device__ float g_C[(size_t)NSTEP * NPAD * CROW];   // ~29 MB
__device__ float4 g_A[NSTEP * BB];                   // xi0,xi1,xi2, ef
__device__ float4 g_M[NSTEP * BB];                   // m0,m1,m2, bits(ridx|d<<8)
__device__ float  g_part[(NSTEP + 1) * BB];

// upper bound on non-decreasing 80-row: #(row[j] <= u)
__device__ __forceinline__ int ubound80(const float* __restrict__ row, float u) {
    int lo = 0, hi = 80;
    while (lo < hi) {
        int mid = (lo + hi) >> 1;
        if (row[mid] <= u) lo = mid + 1; else hi = mid;
    }
    return lo;
}

// ---------------- tables (+ hist zero) ----------------
__global__ void k_tables() {
    int tid = threadIdx.x;
    for (int i = tid; i < RR * 80; i += 64) g_hist[i] = 0;
    int r = tid;
    if (r >= RR) return;
    float cum = 0.f, slam = 0.f, smu = 0.f;
    for (int k = 1; k <= GAP; k++) {
        float kk = (float)k;
        float lam = ((r + RMIN + k) <= RMIN + GAP) ? 1.0f / (kk * kk) : 0.0f;
        slam += lam; cum += lam;
        g_jm[r * 80 + (k - 1)] = cum;
    }
    for (int k = 1; k <= GAP; k++) {
        float kk = (float)k;
        float mu = ((r + RMIN - k) >= RMIN) ? 1.0f / (kk * kk) : 0.0f;
        smu += mu; cum += mu;
        g_jm[r * 80 + GAP + (k - 1)] = cum;
    }
    g_cr[r] = cum;
    g_cfr[r] = slam + smu - cum;
    for (int j = 0; j < 80; j++) g_jm[r * 80 + j] /= cum;
}

__global__ void k_mc_hist(const float* __restrict__ u_mc) {
    int i = blockIdx.x * blockDim.x + threadIdx.x;
    if (i >= MCN * RR) return;
    int r = i % RR;
    int ind = ubound80(&g_jm[r * 80], u_mc[i]);
    atomicAdd(&g_hist[r * 80 + ind], 1);
}

__global__ void k_mc_combine(const float* __restrict__ jump_l) {
    int idx = blockIdx.x * blockDim.x + threadIdx.x;
    if (idx >= RR * PP) return;
    int r = idx / PP, p = idx % PP;
    float s = 0.f;
    for (int b = 0; b < 80; b++) {
        int c = g_hist[r * 80 + b];
        if (c) s += (float)c * jump_l[b * PP + p];
    }
    g_mcjump[idx] = s * (1.0f / (float)MCN) * g_cr[r];
}

// ---------------- W3E build: one CTA per (r-group of 6, t); t=NSTEP -> u-net ----------------
#define RGRP 6
__global__ void __launch_bounds__(256, 1)
k_build_w3e(const float* __restrict__ guW3, const float* __restrict__ gub3,
            const float* __restrict__ guE,
            const float* __restrict__ uW3, const float* __restrict__ ub3,
            const float* __restrict__ uE) {
    __shared__ float sW[64 * 129];
    __shared__ float sE6[RGRP * 384];
    int rb = blockIdx.x * RGRP, t = blockIdx.y, tid = threadIdx.x;
    int nr = (RR - rb < RGRP) ? (RR - rb) : RGRP;
    if (t < NSTEP) {
        for (int idx = tid; idx < 8192; idx += 256) {
            int j = idx >> 7, p = idx & 127;
            sW[j * 129 + p] = guW3[(size_t)t * 8192 + idx];
        }
        for (int idx = tid; idx < nr * 384; idx += 256)
            sE6[idx] = guE[((size_t)t * RR + rb) * 384 + idx];
        __syncthreads();
        // outputs: nr*192; lane map: j = idx&63 (conflict-free), o = (idx>>6)%3
        for (int idx = tid; idx < nr * 192; idx += 256) {
            int rr = idx / 192, c = idx - rr * 192;
            int j = c & 63, o = c >> 6;
            const float* w = sW + j * 129;
            const float* e = sE6 + rr * 384 + o;
            float acc = 0.f;
#pragma unroll 8
            for (int p = 0; p < 128; p++) acc = fmaf(w[p], e[p * 3], acc);
            g_W3Eg[((size_t)t * RR + rb + rr) * 192 + j * 3 + o] = acc;
        }
        if (tid < nr * 3) {
            int rr = tid / 3, o = tid - rr * 3;
            const float* b = gub3 + t * 128;
            const float* e = sE6 + rr * 384 + o;
            float a = 0.f;
#pragma unroll 8
            for (int p = 0; p < 128; p++) a = fmaf(b[p], e[p * 3], a);
            g_b3Eg[(t * RR + rb + rr) * 3 + o] = a;
        }
    } else {
        for (int idx = tid; idx < 8192; idx += 256) {
            int j = idx >> 7, p = idx & 127;
            sW[j * 129 + p] = uW3[idx];
        }
        for (int idx = tid; idx < nr * 128; idx += 256) sE6[idx] = uE[rb * 128 + idx];
        __syncthreads();
        for (int idx = tid; idx < nr * 64; idx += 256) {
            int rr = idx >> 6, j = idx & 63;
            const float* w = sW + j * 129;
            const float* e = sE6 + rr * 128;
            float acc = 0.f;
#pragma unroll 8
            for (int p = 0; p < 128; p++) acc = fmaf(w[p], e[p], acc);
            g_W3Eu[(rb + rr) * 64 + j] = acc;
        }
        if (tid < nr) {
            const float* e = sE6 + tid * 128;
            float acc = 0.f;
#pragma unroll 8
            for (int p = 0; p < 128; p++) acc = fmaf(ub3[p], e[p], acc);
            g_b3Eu[rb + tid] = acc;
        }
    }
}

// ---------------- C table build: FFMA2 + coalesced float4 stores ----------------
#define CPAD 68
#define SMEM_C_FLOATS (2 * 128 * CPAD)
__global__ void __launch_bounds__(256, 1)
k_build_C(const float* __restrict__ jxW3, const float* __restrict__ jxb3,
          const float* __restrict__ jump_r, const float* __restrict__ jump_l) {
    extern __shared__ float smc[];
    float* smA = smc;                 // [128][68]: smA[p][j]
    float* smB = smc + 128 * CPAD;    // [128][68]: smB[p][n]
    int nblk = blockIdx.x, t = blockIdx.y, tid = threadIdx.x;

    for (int idx = tid; idx < 8192; idx += 256) {
        int j = idx >> 7, p = idx & 127;
        smA[p * CPAD + j] = jxW3[(size_t)t * 8192 + idx];
    }
    for (int idx = tid; idx < 8192; idx += 256) {
        int n = idx >> 7, p = idx & 127;
        int n_g = nblk * 64 + n;
        float b = 0.f;
        if (n_g < RR * 81) {
            int r = n_g / 81, d = n_g - r * 81;
            float jl = 0.f;
            if (d > 40)      jl = jump_l[(d - 41) * PP + p];
            else if (d < 40) jl = jump_l[(79 - d) * PP + p];
            b = jump_r[r * PP + p] * (jl - g_mcjump[r * PP + p] * DT_F);
        }
        smB[p * CPAD + n] = b;
    }
    __syncthreads();

    int tx = tid & 15, ty = tid >> 4;   // tx -> j-quad (fast axis), ty -> n-quad
    ull acc[4][2];
#pragma unroll
    for (int n = 0; n < 4; n++) { acc[n][0] = 0ull; acc[n][1] = 0ull; }
#pragma unroll 4
    for (int p = 0; p < 128; p++) {
        longlong2 aj = *(const longlong2*)(smA + p * CPAD + tx * 4);
        float4 bn = *(const float4*)(smB + p * CPAD + ty * 4);
        ull b0 = pack2(bn.x, bn.x), b1 = pack2(bn.y, bn.y);
        ull b2 = pack2(bn.z, bn.z), b3 = pack2(bn.w, bn.w);
        acc[0][0] = fma2(b0, (ull)aj.x, acc[0][0]);
        acc[0][1] = fma2(b0, (ull)aj.y, acc[0][1]);
        acc[1][0] = fma2(b1, (ull)aj.x, acc[1][0]);
        acc[1][1] = fma2(b1, (ull)aj.y, acc[1][1]);
        acc[2][0] = fma2(b2, (ull)aj.x, acc[2][0]);
        acc[2][1] = fma2(b2, (ull)aj.y, acc[2][1]);
        acc[3][0] = fma2(b3, (ull)aj.x, acc[3][0]);
        acc[3][1] = fma2(b3, (ull)aj.y, acc[3][1]);
    }
#pragma unroll
    for (int n = 0; n < 4; n++) {
        int n_g = nblk * 64 + ty * 4 + n;
        float2 lo = unpk(acc[n][0]);
        float2 hi = unpk(acc[n][1]);
        float4 v; v.x = lo.x; v.y = lo.y; v.z = hi.x; v.w = hi.y;
        *(float4*)(g_C + ((size_t)t * NPAD + n_g) * CROW + tx * 4) = v;
    }
    if (tid < 64) {
        int n_g = nblk * 64 + tid;
        const float* b3 = jxb3 + t * 128;
        float c0 = 0.f;
#pragma unroll 4
        for (int p = 0; p < 128; p++) c0 = fmaf(b3[p], smB[p * CPAD + tid], c0);
        size_t base = ((size_t)t * NPAD + n_g) * CROW;
        g_C[base + 64] = c0;
        g_C[base + 65] = 0.f; g_C[base + 66] = 0.f; g_C[base + 67] = 0.f;
    }
}

// ---------------- geometry pass: trajectory only, NN-free ----------------
__global__ void __launch_bounds__(256)
k_geom(const int* __restrict__ rt0, const float* __restrict__ xt0,
       const float* __restrict__ dBt, const float* __restrict__ u_jump,
       const float* __restrict__ u_size, float* __restrict__ out) {
    __shared__ float sJM[RR * 80];
    __shared__ float sCR[RR];
    __shared__ float sCF[RR];
    int tid = threadIdx.x;
    for (int idx = tid; idx < RR * 80; idx += 256) sJM[idx] = g_jm[idx];
    for (int idx = tid; idx < RR; idx += 256) {
        sCR[idx] = g_cr[idx];
        sCF[idx] = g_cfr[idx];
    }
    __syncthreads();

    int i = blockIdx.x * 256 + tid;
    const float sqDT = 0.17677669529663688985f;   // sqrt(1/32)
    const float sq2D = 1.41421356237309504880f;   // sqrt(2)
    int rt = rt0[i];
    float x0 = xt0[i * 3 + 0], x1 = xt0[i * 3 + 1], x2 = xt0[i * 3 + 2];
    float xi0 = x0, xi1 = x1, xi2 = x2;
    float sgn = 1.f, fun = 0.f;

#pragma unroll 1
    for (int t = 0; t < NSTEP; t++) {
        int ridx = rt - RMIN;
        float uj = u_jump[t * BB + i];
        int drt = 0;
        if (uj < sCR[ridx] * DT_F) {
            int ind = ubound80(sJM + ridx * 80, u_size[t * BB + i]);
            drt = (ind < GAP) ? (ind + 1) : -(ind - GAP + 1);
        }

        float rn = sqrtf(x0 * x0 + x1 * x1 + x2 * x2);
        float cz = fminf(fmaxf(x2 / rn, -1.0f), 1.0f);
        float theta = acosf(cz) - 0.5f * PI_F;
        float phi = atan2f(x1, x0);
        float st, ct, sp, cpv;
        __sincosf(theta, &st, &ct);
        __sincosf(phi, &sp, &cpv);
        float T00 = cpv * ct, T01 = -sp,  T02 = cpv * st;
        float T10 = sp * ct,  T11 = cpv,  T12 = sp * st;
        float T20 = -st,      T22 = ct;

        float2 db = ((const float2*)dBt)[t * BB + i];
        float dB0 = db.x * sqDT, dB1 = db.y * sqDT;
        float rtf = (float)rt;
        float c1 = sq2D / rtf;
        float ef = __expf(-fun);

        float m0 = ef * c1 * (T01 * dB1 - T02 * dB0);
        float m1 = ef * c1 * (T11 * dB1 - T12 * dB0);
        float m2 = -ef * c1 * sgn * T22 * dB0;
        float4 av; av.x = xi0; av.y = xi1; av.z = xi2; av.w = ef;
        g_A[t * BB + i] = av;
        float4 mv; mv.x = m0; mv.y = m1; mv.z = m2;
        mv.w = __int_as_float(ridx | ((drt + 40) << 8));
        g_M[t * BB + i] = mv;

        fun += sCF[ridx] * DT_F;

        float dX20 = c1 * dB0, dX21 = c1 * dB1;
        float th_d = dX20 + 0.5f * PI_F;
        float sth, cth, sph, cph;
        __sincosf(th_d, &sth, &cth);
        __sincosf(dX21, &sph, &cph);
        float d30 = sth * cph - 1.0f;
        float d31 = sth * sph;
        float d32 = cth;
        float dX0 = T00 * d30 + T01 * d31 + T02 * d32;
        float dX1 = T10 * d30 + T11 * d31 + T12 * d32;
        float dX2 = T20 * d30 + T22 * d32;     // T21 = 0
        x0 += dX0; x1 += dX1; x2 += dX2;
        xi0 += dX0; xi1 += dX1; xi2 += sgn * dX2;
        rt += drt;
        if (xi2 < 0.f) { xi2 = -xi2; sgn = -sgn; }
    }

    float ef = __expf(-fun);
    out[BB + i] = (xi0 * xi0 + xi1 * xi1 + xi2 * xi2) / (float)rt * ef;
}

// ---------------- helpers ----------------
__device__ __forceinline__ void cp4s(float* dst, const float* __restrict__ src,
                                     int nfl, int tid) {
    const float4* s = (const float4*)src;
    float4* d = (float4*)dst;
    int n4 = nfl >> 2;
    for (int i = tid; i < n4; i += 256) d[i] = s[i];
}

// tanh = 1 - 2/(1+e^{2x}); clamp-free (inf -> 1, underflow -> -1)
__device__ __forceinline__ float tanh_fast(float x) {
    float e = __expf(2.0f * x);
    float r = __fdividef(1.0f, e + 1.0f);
    return fmaf(-2.0f, r, 1.0f);
}

// layer1: x(3) -> tanh(64); weights W1 @0 [3][64], b1 @192
__device__ __forceinline__ void layer1(const float* __restrict__ W,
                                       float x0, float x1, float x2, float* h1) {
#pragma unroll
    for (int j = 0; j < 64; j += 4) {
        float4 wa = *(const float4*)(W + j);
        float4 wb = *(const float4*)(W + 64 + j);
        float4 wc = *(const float4*)(W + 128 + j);
        float4 bb = *(const float4*)(W + 192 + j);
        h1[j + 0] = tanh_fast(fmaf(x0, wa.x, fmaf(x1, wb.x, fmaf(x2, wc.x, bb.x))));
        h1[j + 1] = tanh_fast(fmaf(x0, wa.y, fmaf(x1, wb.y, fmaf(x2, wc.y, bb.y))));
        h1[j + 2] = tanh_fast(fmaf(x0, wa.z, fmaf(x1, wb.z, fmaf(x2, wc.z, bb.z))));
        h1[j + 3] = tanh_fast(fmaf(x0, wa.w, fmaf(x1, wb.w, fmaf(x2, wc.w, bb.w))));
    }
}

// layer2 16-output pass via packed FFMA2: y[16] = tanh(h1 @ W2[:, cbase:cbase+16] + b2)
__device__ __forceinline__ void layer2_pass16(const float* __restrict__ W2,
                                              const float* __restrict__ b2,
                                              const float* __restrict__ h1,
                                              int cbase, float* y) {
    ull A[8];
    {
        const longlong2* bb = (const longlong2*)(b2 + cbase);
#pragma unroll
        for (int q = 0; q < 4; q++) {
            longlong2 v = bb[q];
            A[2 * q] = (ull)v.x; A[2 * q + 1] = (ull)v.y;
        }
    }
#pragma unroll
    for (int j = 0; j < 64; j++) {
        ull hp = pack2(h1[j], h1[j]);
        const longlong2* w = (const longlong2*)(W2 + j * 64 + cbase);
#pragma unroll
        for (int q = 0; q < 4; q++) {
            longlong2 wv = w[q];
            A[2 * q]     = fma2(hp, (ull)wv.x, A[2 * q]);
            A[2 * q + 1] = fma2(hp, (ull)wv.y, A[2 * q + 1]);
        }
    }
#pragma unroll
    for (int q = 0; q < 8; q++) {
        float2 f = unpk(A[q]);
        y[2 * q]     = tanh_fast(f.x);
        y[2 * q + 1] = tanh_fast(f.y);
    }
}

// ---------------- NN kernel: grid (NCH chunks, t) ----------------
// smem: gW 4416 | jW 4416 | E 7872 | B3E 128  = 16832 floats
#define SN_GW   0
#define SN_JW   4416
#define SN_E    8832
#define SN_B3E  16704
#define SN_TOT  16832
__global__ void __launch_bounds__(256, 2)
k_nn(const float* __restrict__ xt0, const int* __restrict__ rt0,
     const float* __restrict__ uW1, const float* __restrict__ ub1,
     const float* __restrict__ uW2, const float* __restrict__ ub2,
     const float* __restrict__ guW1, const float* __restrict__ gub1,
     const float* __restrict__ guW2, const float* __restrict__ gub2,
     const float* __restrict__ jxW1, const float* __restrict__ jxb1,
     const float* __restrict__ jxW2, const float* __restrict__ jxb2) {
    extern __shared__ float sm[];
    int t = blockIdx.y, tid = threadIdx.x;

    if (t < NSTEP) {
        cp4s(sm + SN_GW,        guW1 + t * 192,  192,  tid);
        cp4s(sm + SN_GW + 192,  gub1 + t * 64,   64,   tid);
        cp4s(sm + SN_GW + 256,  guW2 + t * 4096, 4096, tid);
        cp4s(sm + SN_GW + 4352, gub2 + t * 64,   64,   tid);
        cp4s(sm + SN_JW,        jxW1 + t * 192,  192,  tid);
        cp4s(sm + SN_JW + 192,  jxb1 + t * 64,   64,   tid);
        cp4s(sm + SN_JW + 256,  jxW2 + t * 4096, 4096, tid);
        cp4s(sm + SN_JW + 4352, jxb2 + t * 64,   64,   tid);
        const float* wsrc = g_W3Eg + (size_t)t * RR * 192;
        for (int idx = tid; idx < RR * 192; idx += 256) {
            int r = idx / 192, c = idx - r * 192;
            sm[SN_E + c * 41 + r] = wsrc[idx];
        }
        const float* bsrc = g_b3Eg + t * RR * 3;
        for (int idx = tid; idx < RR * 3; idx += 256) {
            int r = idx / 3, o = idx - r * 3;
            sm[SN_B3E + o * 41 + r] = bsrc[idx];
        }
    } else {
        cp4s(sm + SN_GW, uW1, 192, tid);
        cp4s(sm + SN_GW + 192, ub1, 64, tid);
        cp4s(sm + SN_GW + 256, uW2, 4096, tid);
        cp4s(sm + SN_GW + 4352, ub2, 64, tid);
        for (int idx = tid; idx < RR * 64; idx += 256) {
            int r = idx >> 6, j = idx & 63;
            sm[SN_E + j * 41 + r] = g_W3Eu[idx];
        }
        for (int idx = tid; idx < RR; idx += 256) sm[SN_B3E + idx] = g_b3Eu[idx];
    }
    __syncthreads();

    float h1[64];
    float y[16];

    if (t < NSTEP) {
#pragma unroll 1
        for (int k = 0; k < 8; k++) {
            int i = blockIdx.x * 256 + k * (NCH * 256) + tid;
            if (i >= BB) break;
            float4 av = g_A[t * BB + i];
            float4 mv = g_M[t * BB + i];
            int bits = __float_as_int(mv.w);
            int ridx = bits & 0xFF;
            int n = ridx * 81 + (bits >> 8);
            const float* crow = g_C + ((size_t)t * NPAD + n) * CROW;

            // ---- g-net ----
            layer1(sm + SN_GW, av.x, av.y, av.z, h1);
            float gu0 = sm[SN_B3E + ridx];
            float gu1 = sm[SN_B3E + 41 + ridx];
            float gu2 = sm[SN_B3E + 82 + ridx];
#pragma unroll 1
            for (int pass = 0; pass < 4; pass++) {
                layer2_pass16(sm + SN_GW + 256, sm + SN_GW + 4352, h1, pass * 16, y);
#pragma unroll
                for (int q = 0; q < 16; q++) {
                    const float* e = sm + SN_E + ((pass * 16 + q) * 3) * 41 + ridx;
                    gu0 = fmaf(y[q], e[0], gu0);
                    gu1 = fmaf(y[q], e[41], gu1);
                    gu2 = fmaf(y[q], e[82], gu2);
                }
            }

            // ---- j-net ----
            layer1(sm + SN_JW, av.x, av.y, av.z, h1);
            float jmp = crow[64];   // c0
            const float4* crow4 = (const float4*)crow;
#pragma unroll 1
            for (int pass = 0; pass < 4; pass++) {
                layer2_pass16(sm + SN_JW + 256, sm + SN_JW + 4352, h1, pass * 16, y);
                float4 c0 = crow4[pass * 4 + 0];
                float4 c1 = crow4[pass * 4 + 1];
                float4 c2 = crow4[pass * 4 + 2];
                float4 c3 = crow4[pass * 4 + 3];
                jmp = fmaf(y[0],  c0.x, jmp); jmp = fmaf(y[1],  c0.y, jmp);
                jmp = fmaf(y[2],  c0.z, jmp); jmp = fmaf(y[3],  c0.w, jmp);
                jmp = fmaf(y[4],  c1.x, jmp); jmp = fmaf(y[5],  c1.y, jmp);
                jmp = fmaf(y[6],  c1.z, jmp); jmp = fmaf(y[7],  c1.w, jmp);
                jmp = fmaf(y[8],  c2.x, jmp); jmp = fmaf(y[9],  c2.y, jmp);
                jmp = fmaf(y[10], c2.z, jmp); jmp = fmaf(y[11], c2.w, jmp);
                jmp = fmaf(y[12], c3.x, jmp); jmp = fmaf(y[13], c3.y, jmp);
                jmp = fmaf(y[14], c3.z, jmp); jmp = fmaf(y[15], c3.w, jmp);
            }

            g_part[t * BB + i] = gu0 * mv.x + gu1 * mv.y + gu2 * mv.z + av.w * jmp;
        }
    } else {
        // u0 slice
#pragma unroll 1
        for (int k = 0; k < 8; k++) {
            int i = blockIdx.x * 256 + k * (NCH * 256) + tid;
            if (i >= BB) break;
            float x0 = xt0[i * 3 + 0], x1 = xt0[i * 3 + 1], x2 = xt0[i * 3 + 2];
            int ridx = rt0[i] - RMIN;
            layer1(sm + SN_GW, x0, x1, x2, h1);
            float u = sm[SN_B3E + ridx];
#pragma unroll 1
            for (int pass = 0; pass < 4; pass++) {
                layer2_pass16(sm + SN_GW + 256, sm + SN_GW + 4352, h1, pass * 16, y);
#pragma unroll
                for (int q = 0; q < 16; q++)
                    u = fmaf(y[q], sm[SN_E + (pass * 16 + q) * 41 + ridx], u);
            }
            g_part[NSTEP * BB + i] = u;
        }
    }
}

// ---------------- reduction ----------------
__global__ void __launch_bounds__(256)
k_reduce(float* __restrict__ out) {
    int i = blockIdx.x * 256 + threadIdx.x;
    float s = g_part[NSTEP * BB + i];
#pragma unroll 1
    for (int t = 0; t < NSTEP; t++) s += g_part[t * BB + i];
    out[i] = s;
}

// ---------------- launcher ----------------
extern "C" void kernel_launch(void* const* d_in, const int* in_sizes, int n_in,
                              void* d_out, int out_size) {
    const int*   rt0    = (const int*)d_in[1];
    const float* xt0    = (const float*)d_in[2];
    const float* dBt    = (const float*)d_in[3];
    const float* u_jump = (const float*)d_in[4];
    const float* u_size = (const float*)d_in[5];
    const float* u_mc   = (const float*)d_in[6];
    const float* uW1 = (const float*)d_in[7];
    const float* ub1 = (const float*)d_in[8];
    const float* uW2 = (const float*)d_in[9];
    const float* ub2 = (const float*)d_in[10];
    const float* uW3 = (const float*)d_in[11];
    const float* ub3 = (const float*)d_in[12];
    const float* uE  = (const float*)d_in[13];
    const float* guW1 = (const float*)d_in[14];
    const float* gub1 = (const float*)d_in[15];
    const float* guW2 = (const float*)d_in[16];
    const float* gub2 = (const float*)d_in[17];
    const float* guW3 = (const float*)d_in[18];
    const float* gub3 = (const float*)d_in[19];
    const float* guE  = (const float*)d_in[20];
    const float* jxW1 = (const float*)d_in[21];
    const float* jxb1 = (const float*)d_in[22];
    const float* jxW2 = (const float*)d_in[23];
    const float* jxb2 = (const float*)d_in[24];
    const float* jxW3 = (const float*)d_in[25];
    const float* jxb3 = (const float*)d_in[26];
    const float* jump_r = (const float*)d_in[27];
    const float* jump_l = (const float*)d_in[28];
    float* out = (float*)d_out;

    cudaFuncSetAttribute(k_build_C, cudaFuncAttributeMaxDynamicSharedMemorySize,
                         SMEM_C_FLOATS * 4);
    cudaFuncSetAttribute(k_nn, cudaFuncAttributeMaxDynamicSharedMemorySize,
                         SN_TOT * 4);

    k_tables<<<1, 64>>>();
    k_mc_hist<<<(MCN * RR + 255) / 256, 256>>>(u_mc);
    k_mc_combine<<<(RR * PP + 127) / 128, 128>>>(jump_l);
    k_build_w3e<<<dim3((RR + RGRP - 1) / RGRP, NSTEP + 1), 256>>>(
        guW3, gub3, guE, uW3, ub3, uE);
    k_build_C<<<dim3(NBLK, NSTEP), 256, SMEM_C_FLOATS * 4>>>(jxW3, jxb3, jump_r, jump_l);
    k_geom<<<BB / 256, 256>>>(rt0, xt0, dBt, u_jump, u_size, out);
    k_nn<<<dim3(NCH, NSTEP + 1), 256, SN_TOT * 4>>>(
        xt0, rt0, uW1, ub1, uW2, ub2,
        guW1, gub1, guW2, gub2,
        jxW1, jxb1, jxW2, jxb2);
    k_reduce<<<BB / 256, 256>>>(out);
    (void)in_sizes; (void)n_in; (void)out_size;
}